// round 2
// baseline (speedup 1.0000x reference)
#include <cuda_runtime.h>
#include <cuda_bf16.h>
#include <math.h>

#define NODE   1280
#define PROJ   2560
#define ATTND  256
#define NREL   129
#define NL     4
#define BB     2
#define LL     1024
#define GVA_N  (2*PROJ + ATTND)   // 5376
#define ADALN_N (3*NODE)          // 3840
#define ROWS   (BB*LL)            // 2048

// ---------------- scratch (device globals; no allocation allowed) ----------
__device__ float d_sc  [BB*NODE];
__device__ float d_gba [BB*ADALN_N];
__device__ float d_x   [ROWS*NODE];
__device__ float d_h   [ROWS*GVA_N];
__device__ float d_q   [ROWS*ATTND];
__device__ float d_k   [ROWS*ATTND];
__device__ float d_attn[(long)BB*LL*LL];
__device__ float d_av  [ROWS*PROJ];
__device__ float d_node[ROWS*NODE];

// ---------------- helpers ---------------------------------------------------
__device__ __forceinline__ float siluf(float x) { return x / (1.f + __expf(-x)); }
__device__ __forceinline__ float warpMax(float v) {
    #pragma unroll
    for (int o = 16; o > 0; o >>= 1) v = fmaxf(v, __shfl_xor_sync(0xffffffffu, v, o));
    return v;
}
__device__ __forceinline__ float warpSum(float v) {
    #pragma unroll
    for (int o = 16; o > 0; o >>= 1) v += __shfl_xor_sync(0xffffffffu, v, o);
    return v;
}

// ---------------- silu(cond) -------------------------------------------------
__global__ void silu_vec_k(const float* __restrict__ c, float* __restrict__ sc, int n) {
    int i = blockIdx.x * 256 + threadIdx.x;
    if (i < n) sc[i] = siluf(c[i]);
}

// ---------------- adaLN: gba = silu(cond) @ w_adaln + b ---------------------
__global__ void adaln_k(const float* __restrict__ sc, const float* __restrict__ w,
                        const float* __restrict__ bvec, float* __restrict__ gba) {
    int idx = blockIdx.x * 256 + threadIdx.x;        // 0..7679
    int b   = idx / ADALN_N;
    int col = idx - b * ADALN_N;
    const float* s = sc + b * NODE;
    float acc = bvec[col];
    #pragma unroll 8
    for (int k = 0; k < NODE; k++)
        acc = fmaf(s[k], w[(long)k * ADALN_N + col], acc);
    gba[idx] = acc;
}

// ---------------- LayerNorm + modulate --------------------------------------
__global__ __launch_bounds__(256) void ln_mod_k(const float* __restrict__ node,
                                                const float* __restrict__ gba,
                                                float* __restrict__ x) {
    const int row = blockIdx.x;
    const int b   = row >> 10;
    const float* p = node + (long)row * NODE;
    float vals[5];
    float s = 0.f, sq = 0.f;
    #pragma unroll
    for (int i = 0; i < 5; i++) {
        float v = p[threadIdx.x + i * 256];
        vals[i] = v; s += v; sq += v * v;
    }
    __shared__ float rs[8], rq[8];
    s = warpSum(s); sq = warpSum(sq);
    if ((threadIdx.x & 31) == 0) { rs[threadIdx.x >> 5] = s; rq[threadIdx.x >> 5] = sq; }
    __syncthreads();
    float ts = 0.f, tq = 0.f;
    #pragma unroll
    for (int i = 0; i < 8; i++) { ts += rs[i]; tq += rq[i]; }
    const float mean = ts * (1.f / NODE);
    const float var  = tq * (1.f / NODE) - mean * mean;
    const float rstd = rsqrtf(var + 1e-5f);
    const float* g = gba + (long)b * ADALN_N;
    float* xo = x + (long)row * NODE;
    #pragma unroll
    for (int i = 0; i < 5; i++) {
        int c = threadIdx.x + i * 256;
        float v = (vals[i] - mean) * rstd;
        xo[c] = v * (1.f + g[c]) + g[NODE + c];
    }
}

// ---------------- main SGEMM: 128x128x8, 8x8/thread, batched via z ----------
// MODE 1: C = silu(acc + bias[n])
// MODE 2: C = acc * aux[m,n]                      (gates)
// MODE 3: C = (acc + bias[n])*(1+alpha[n]) + aux  (out proj + residual)
template <int MODE>
__global__ __launch_bounds__(256) void sgemm_k(
    int K,
    const float* __restrict__ A, int lda, long sA,
    const float* __restrict__ B, int ldb, long sB,
    float* __restrict__ C, int ldc, long sC,
    const float* __restrict__ bias,
    const float* __restrict__ aux, int ldaux, long sAux,
    const float* __restrict__ alphaP, int sAlpha) {
    const int z = blockIdx.z;
    A += z * sA; B += z * sB; C += z * sC;
    if (MODE == 2 || MODE == 3) aux += z * sAux;
    const float* alpha = (MODE == 3) ? (alphaP + (long)z * sAlpha) : nullptr;

    __shared__ float As[8][128];
    __shared__ float Bs[8][128];

    const int tid  = threadIdx.x;
    const int a_r  = tid >> 1, a_c = (tid & 1) << 2;
    const int b_r  = tid >> 5, b_c = (tid & 31) << 2;
    const int trow = tid >> 4, tcol = tid & 15;

    const float* Ap = A + ((long)blockIdx.y * 128 + a_r) * lda + a_c;
    const float* Bp = B + (long)b_r * ldb + blockIdx.x * 128 + b_c;

    float acc[8][8] = {};
    for (int k0 = 0; k0 < K; k0 += 8) {
        float4 av = *(const float4*)(Ap + k0);
        float4 bv = *(const float4*)(Bp + (long)k0 * ldb);
        As[a_c + 0][a_r] = av.x; As[a_c + 1][a_r] = av.y;
        As[a_c + 2][a_r] = av.z; As[a_c + 3][a_r] = av.w;
        *(float4*)&Bs[b_r][b_c] = bv;
        __syncthreads();
        #pragma unroll
        for (int kk = 0; kk < 8; kk++) {
            float ra[8], rb[8];
            #pragma unroll
            for (int i = 0; i < 8; i++) ra[i] = As[kk][trow * 8 + i];
            #pragma unroll
            for (int j = 0; j < 8; j++) rb[j] = Bs[kk][tcol * 8 + j];
            #pragma unroll
            for (int i = 0; i < 8; i++)
                #pragma unroll
                for (int j = 0; j < 8; j++)
                    acc[i][j] = fmaf(ra[i], rb[j], acc[i][j]);
        }
        __syncthreads();
    }

    const int r0 = blockIdx.y * 128 + trow * 8;
    const int c0 = blockIdx.x * 128 + tcol * 8;
    #pragma unroll
    for (int i = 0; i < 8; i++) {
        long r = r0 + i;
        #pragma unroll
        for (int j = 0; j < 8; j += 4) {
            int c = c0 + j;
            float4 v = make_float4(acc[i][j], acc[i][j + 1], acc[i][j + 2], acc[i][j + 3]);
            if (MODE == 1) {
                v.x = siluf(v.x + bias[c + 0]); v.y = siluf(v.y + bias[c + 1]);
                v.z = siluf(v.z + bias[c + 2]); v.w = siluf(v.w + bias[c + 3]);
            } else if (MODE == 2) {
                const float4 g = *(const float4*)(aux + r * (long)ldaux + c);
                v.x *= g.x; v.y *= g.y; v.z *= g.z; v.w *= g.w;
            } else if (MODE == 3) {
                const float4 sres = *(const float4*)(aux + r * (long)ldaux + c);
                v.x = (v.x + bias[c + 0]) * (1.f + alpha[c + 0]) + sres.x;
                v.y = (v.y + bias[c + 1]) * (1.f + alpha[c + 1]) + sres.y;
                v.z = (v.z + bias[c + 2]) * (1.f + alpha[c + 2]) + sres.z;
                v.w = (v.w + bias[c + 3]) * (1.f + alpha[c + 3]) + sres.w;
            }
            *(float4*)(C + r * (long)ldc + c) = v;
        }
    }
}

// ---------------- q/k build + RoPE (q pre-scaled by qk_scaling) -------------
__global__ void qk_rope_k(const float* __restrict__ h, const float* __restrict__ mw,
                          const float* __restrict__ mb, const float* __restrict__ scal,
                          float* __restrict__ q, float* __restrict__ k) {
    const int row = blockIdx.x;
    const int t   = threadIdx.x;           // 0..127
    const int pos = row & (LL - 1);
    const float* base = h + (long)row * GVA_N + 2 * PROJ;
    float b0 = base[t], b1 = base[t + 128];
    float q0 = fmaf(b0, mw[t],       mb[t]);
    float q1 = fmaf(b1, mw[t + 128], mb[t + 128]);
    float k0 = fmaf(b0, mw[256 + t],       mb[256 + t]);
    float k1 = fmaf(b1, mw[256 + t + 128], mb[256 + t + 128]);
    // freq = 10000^(-2t/256) = 2^(-log2(1e4)*t/128)
    float freq = exp2f(-(float)t * (13.287712379549449f / 128.f));
    float ang = (float)pos * freq;
    float sn, cs; sincosf(ang, &sn, &cs);
    float sc = scal[row];
    q[(long)row * 256 + t]       = (q0 * cs - q1 * sn) * sc;
    q[(long)row * 256 + t + 128] = (q1 * cs + q0 * sn) * sc;
    k[(long)row * 256 + t]       =  k0 * cs - k1 * sn;
    k[(long)row * 256 + t + 128] =  k1 * cs + k0 * sn;
}

// ---------------- logits = q.k^T + bias + relpos (NT gemm 64x64x16) ---------
__global__ __launch_bounds__(256) void qk_logits_k(
    const float* __restrict__ Q, const float* __restrict__ Km,
    const float* __restrict__ bias, const float* __restrict__ rel,
    float* __restrict__ S) {
    const int z = blockIdx.z;
    const float* Qb = Q + (long)z * LL * ATTND;
    const float* Kb = Km + (long)z * LL * ATTND;
    float* Sb = S + (long)z * LL * LL;
    __shared__ float Qs[16][64];
    __shared__ float Ks[16][64];
    const int tid = threadIdx.x;
    const int lr = tid >> 2, lc = (tid & 3) << 2;
    const int trow = tid >> 4, tcol = tid & 15;
    const int i0 = blockIdx.y * 64, j0 = blockIdx.x * 64;
    float acc[4][4] = {};
    for (int d0 = 0; d0 < ATTND; d0 += 16) {
        float4 qv = *(const float4*)(Qb + (long)(i0 + lr) * ATTND + d0 + lc);
        float4 kv = *(const float4*)(Kb + (long)(j0 + lr) * ATTND + d0 + lc);
        Qs[lc + 0][lr] = qv.x; Qs[lc + 1][lr] = qv.y; Qs[lc + 2][lr] = qv.z; Qs[lc + 3][lr] = qv.w;
        Ks[lc + 0][lr] = kv.x; Ks[lc + 1][lr] = kv.y; Ks[lc + 2][lr] = kv.z; Ks[lc + 3][lr] = kv.w;
        __syncthreads();
        #pragma unroll
        for (int kk = 0; kk < 16; kk++) {
            float ra[4], rb[4];
            #pragma unroll
            for (int i = 0; i < 4; i++) ra[i] = Qs[kk][trow * 4 + i];
            #pragma unroll
            for (int j = 0; j < 4; j++) rb[j] = Ks[kk][tcol * 4 + j];
            #pragma unroll
            for (int i = 0; i < 4; i++)
                #pragma unroll
                for (int j = 0; j < 4; j++)
                    acc[i][j] = fmaf(ra[i], rb[j], acc[i][j]);
        }
        __syncthreads();
    }
    #pragma unroll
    for (int i = 0; i < 4; i++) {
        int gi = i0 + trow * 4 + i;
        #pragma unroll
        for (int j = 0; j < 4; j++) {
            int gj = j0 + tcol * 4 + j;
            int di = gi - gj; di = di < -64 ? -64 : (di > 64 ? 64 : di);
            Sb[(long)gi * LL + gj] = acc[i][j] + bias[z * LL + gj] + rel[di + 64];
        }
    }
}

// ---------------- row softmax over 1024 --------------------------------------
__global__ __launch_bounds__(256) void softmax_k(float* __restrict__ S) {
    float4* p = (float4*)(S + (long)blockIdx.x * LL);
    float4 v = p[threadIdx.x];
    __shared__ float rm[8], rs[8];
    float m = fmaxf(fmaxf(v.x, v.y), fmaxf(v.z, v.w));
    m = warpMax(m);
    if ((threadIdx.x & 31) == 0) rm[threadIdx.x >> 5] = m;
    __syncthreads();
    m = rm[0];
    #pragma unroll
    for (int i = 1; i < 8; i++) m = fmaxf(m, rm[i]);
    v.x = __expf(v.x - m); v.y = __expf(v.y - m);
    v.z = __expf(v.z - m); v.w = __expf(v.w - m);
    float s = v.x + v.y + v.z + v.w;
    s = warpSum(s);
    if ((threadIdx.x & 31) == 0) rs[threadIdx.x >> 5] = s;
    __syncthreads();
    s = 0.f;
    #pragma unroll
    for (int i = 0; i < 8; i++) s += rs[i];
    float inv = 1.f / s;
    v.x *= inv; v.y *= inv; v.z *= inv; v.w *= inv;
    p[threadIdx.x] = v;
}

// ---------------- edge = attn[0] + attn[1] -----------------------------------
__global__ void edge_k(const float* __restrict__ attn, float* __restrict__ e) {
    long i = (long)blockIdx.x * 256 + threadIdx.x;   // over 262144 float4s
    float4 a = ((const float4*)attn)[i];
    float4 b = ((const float4*)(attn + (long)LL * LL))[i];
    ((float4*)e)[i] = make_float4(a.x + b.x, a.y + b.y, a.z + b.z, a.w + b.w);
}

// ---------------- launch ------------------------------------------------------
extern "C" void kernel_launch(void* const* d_in, const int* in_sizes, int n_in,
                              void* d_out, int out_size) {
    const float* node      = (const float*)d_in[0];
    const float* qk_scal   = (const float*)d_in[1];
    const float* bias      = (const float*)d_in[2];
    const float* cond      = (const float*)d_in[3];
    const float* w_gva     = (const float*)d_in[4];
    const float* b_gva     = (const float*)d_in[5];
    const float* mhs_w     = (const float*)d_in[6];
    const float* mhs_b     = (const float*)d_in[7];
    const float* relpos    = (const float*)d_in[8];
    const float* w_out     = (const float*)d_in[9];
    const float* b_out     = (const float*)d_in[10];
    const float* w_adaln   = (const float*)d_in[11];
    const float* b_adaln   = (const float*)d_in[12];
    float* out = (float*)d_out;

    float *sc, *gba, *x, *h, *q, *k, *attn, *av, *nodeb;
    cudaGetSymbolAddress((void**)&sc,    d_sc);
    cudaGetSymbolAddress((void**)&gba,   d_gba);
    cudaGetSymbolAddress((void**)&x,     d_x);
    cudaGetSymbolAddress((void**)&h,     d_h);
    cudaGetSymbolAddress((void**)&q,     d_q);
    cudaGetSymbolAddress((void**)&k,     d_k);
    cudaGetSymbolAddress((void**)&attn,  d_attn);
    cudaGetSymbolAddress((void**)&av,    d_av);
    cudaGetSymbolAddress((void**)&nodeb, d_node);

    cudaMemcpyAsync(nodeb, node, (size_t)ROWS * NODE * sizeof(float),
                    cudaMemcpyDeviceToDevice);
    silu_vec_k<<<(BB * NODE + 255) / 256, 256>>>(cond, sc, BB * NODE);

    for (int l = 0; l < NL; l++) {
        adaln_k<<<(BB * ADALN_N) / 256, 256>>>(
            sc, w_adaln + (long)l * NODE * ADALN_N, b_adaln + l * ADALN_N, gba);

        ln_mod_k<<<ROWS, 256>>>(nodeb, gba, x);

        // h = silu(x @ w_gva + b_gva)   [1024 x 5376 x 1280 per batch]
        sgemm_k<1><<<dim3(GVA_N / 128, LL / 128, BB), 256>>>(
            NODE,
            x, NODE, (long)LL * NODE,
            w_gva + (long)l * NODE * GVA_N, GVA_N, 0L,
            h, GVA_N, (long)LL * GVA_N,
            b_gva + l * GVA_N,
            nullptr, 0, 0L, nullptr, 0);

        qk_rope_k<<<ROWS, 128>>>(h, mhs_w + l * 2 * ATTND, mhs_b + l * 2 * ATTND,
                                 qk_scal, q, k);

        qk_logits_k<<<dim3(LL / 64, LL / 64, BB), 256>>>(
            q, k, bias, relpos + l * NREL, attn);

        softmax_k<<<ROWS, 256>>>(attn);

        if (l == NL - 1)
            edge_k<<<(LL * LL / 4) / 256, 256>>>(attn, out + (long)ROWS * NODE);

        // av = (attn @ values) * gates   [1024 x 2560 x 1024 per batch]
        sgemm_k<2><<<dim3(PROJ / 128, LL / 128, BB), 256>>>(
            LL,
            attn, LL, (long)LL * LL,
            h + PROJ, GVA_N, (long)LL * GVA_N,
            av, PROJ, (long)LL * PROJ,
            nullptr,
            h, GVA_N, (long)LL * GVA_N,     // gates aux
            nullptr, 0);

        // node = (av @ w_out + b_out)*(1+alpha) + shortcut  [1024 x 1280 x 2560]
        float* Cdst = (l == NL - 1) ? out : nodeb;
        sgemm_k<3><<<dim3(NODE / 128, LL / 128, BB), 256>>>(
            PROJ,
            av, PROJ, (long)LL * PROJ,
            w_out + (long)l * PROJ * NODE, NODE, 0L,
            Cdst, NODE, (long)LL * NODE,
            b_out + l * NODE,
            nodeb, NODE, (long)LL * NODE,   // residual aux
            gba + 2 * NODE, ADALN_N);
    }
    (void)in_sizes; (void)n_in; (void)out_size;
}

// round 3
// speedup vs baseline: 2.7557x; 2.7557x over previous
#include <cuda_runtime.h>
#include <cuda_bf16.h>
#include <math.h>

#define NODE   1280
#define PROJ   2560
#define ATTND  256
#define NREL   129
#define NL     4
#define BB     2
#define LL     1024
#define GVA_N  (2*PROJ + ATTND)   // 5376
#define ADALN_N (3*NODE)          // 3840
#define ROWS   (BB*LL)            // 2048
#define KSLICE 4

// ---------------- scratch (device globals; no allocation allowed) ----------
__device__ float d_sc   [BB*NODE];
__device__ float d_part [NL*BB*KSLICE*ADALN_N];
__device__ float d_gba  [NL*BB*ADALN_N];
__device__ float d_x    [ROWS*NODE];
__device__ float d_h    [ROWS*GVA_N];
__device__ float d_q    [ROWS*ATTND];
__device__ float d_k    [ROWS*ATTND];
__device__ float d_attn [(long)BB*LL*LL];
__device__ float d_av   [ROWS*PROJ];
__device__ float d_node [ROWS*NODE];

// ---------------- helpers ---------------------------------------------------
__device__ __forceinline__ float siluf(float x) { return x / (1.f + __expf(-x)); }
__device__ __forceinline__ float warpMax(float v) {
    #pragma unroll
    for (int o = 16; o > 0; o >>= 1) v = fmaxf(v, __shfl_xor_sync(0xffffffffu, v, o));
    return v;
}
__device__ __forceinline__ float warpSum(float v) {
    #pragma unroll
    for (int o = 16; o > 0; o >>= 1) v += __shfl_xor_sync(0xffffffffu, v, o);
    return v;
}
__device__ __forceinline__ unsigned f2tf32(float f) {
    unsigned u; asm("cvt.rna.tf32.f32 %0, %1;" : "=r"(u) : "f"(f)); return u;
}
__device__ __forceinline__ void mma_tf32(float* c, const unsigned* a, const unsigned* b) {
    asm volatile(
        "mma.sync.aligned.m16n8k8.row.col.f32.tf32.tf32.f32 "
        "{%0,%1,%2,%3}, {%4,%5,%6,%7}, {%8,%9}, {%0,%1,%2,%3};"
        : "+f"(c[0]), "+f"(c[1]), "+f"(c[2]), "+f"(c[3])
        : "r"(a[0]), "r"(a[1]), "r"(a[2]), "r"(a[3]), "r"(b[0]), "r"(b[1]));
}

// ---------------- silu(cond) -------------------------------------------------
__global__ void silu_vec_k(const float* __restrict__ c, float* __restrict__ sc, int n) {
    int i = blockIdx.x * 256 + threadIdx.x;
    if (i < n) sc[i] = siluf(c[i]);
}

// ---------------- adaLN for ALL layers, split-K ------------------------------
__global__ void adaln_part_k(const float* __restrict__ sc, const float* __restrict__ w,
                             float* __restrict__ part) {
    // grid: x = ADALN_N/256 (15), y = BB*KSLICE (8), z = NL
    const int l = blockIdx.z, b = blockIdx.y >> 2, ks = blockIdx.y & 3;
    const int col = blockIdx.x * 256 + threadIdx.x;
    const int KC = NODE / KSLICE;      // 320
    const float* s  = sc + b * NODE + ks * KC;
    const float* wp = w + (long)l * NODE * ADALN_N + (long)ks * KC * ADALN_N + col;
    float acc = 0.f;
    #pragma unroll 8
    for (int k = 0; k < KC; k++)
        acc = fmaf(s[k], wp[(long)k * ADALN_N], acc);
    part[((((long)l * BB) + b) * KSLICE + ks) * ADALN_N + col] = acc;
}
__global__ void adaln_reduce_k(const float* __restrict__ part,
                               const float* __restrict__ bvec, float* __restrict__ gba) {
    long idx = (long)blockIdx.x * 256 + threadIdx.x;    // NL*BB*ADALN_N = 30720
    int l = (int)(idx / (BB * ADALN_N));
    int rem = (int)(idx % (BB * ADALN_N));
    int b = rem / ADALN_N, col = rem % ADALN_N;
    const float* p = part + (((long)l * BB + b) * KSLICE) * ADALN_N + col;
    gba[idx] = bvec[l * ADALN_N + col] + p[0] + p[ADALN_N] + p[2 * ADALN_N] + p[3 * ADALN_N];
}

// ---------------- LayerNorm + modulate --------------------------------------
__global__ __launch_bounds__(256) void ln_mod_k(const float* __restrict__ node,
                                                const float* __restrict__ gba,
                                                float* __restrict__ x) {
    const int row = blockIdx.x;
    const int b   = row >> 10;
    const float* p = node + (long)row * NODE;
    float vals[5];
    float s = 0.f, sq = 0.f;
    #pragma unroll
    for (int i = 0; i < 5; i++) {
        float v = p[threadIdx.x + i * 256];
        vals[i] = v; s += v; sq += v * v;
    }
    __shared__ float rs[8], rq[8];
    s = warpSum(s); sq = warpSum(sq);
    if ((threadIdx.x & 31) == 0) { rs[threadIdx.x >> 5] = s; rq[threadIdx.x >> 5] = sq; }
    __syncthreads();
    float ts = 0.f, tq = 0.f;
    #pragma unroll
    for (int i = 0; i < 8; i++) { ts += rs[i]; tq += rq[i]; }
    const float mean = ts * (1.f / NODE);
    const float var  = tq * (1.f / NODE) - mean * mean;
    const float rstd = rsqrtf(var + 1e-5f);
    const float* g = gba + (long)b * ADALN_N;
    float* xo = x + (long)row * NODE;
    #pragma unroll
    for (int i = 0; i < 5; i++) {
        int c = threadIdx.x + i * 256;
        float v = (vals[i] - mean) * rstd;
        xo[c] = v * (1.f + g[c]) + g[NODE + c];
    }
}

// ---------------- tf32 tensor-core GEMM: 128x128x16, mma.m16n8k8 ------------
// MODE 1: C = silu(acc + bias[n])
// MODE 2: C = acc * aux[m,n]
// MODE 3: C = (acc + bias[n])*(1+alpha[n]) + aux[m,n]
// MODE 4: C = acc + bias[n] + rel[clamp(m-n,-64,64)+64]   (logits; bias per-batch)
template <int MODE, bool TRANSB>
__global__ __launch_bounds__(256) void tgemm_k(
    int K,
    const float* __restrict__ A, int lda, long sA,
    const float* __restrict__ B, int ldb, long sB,
    float* __restrict__ C, int ldc, long sC,
    const float* __restrict__ bias,
    const float* __restrict__ aux, int ldaux, long sAux,
    const float* __restrict__ alphaP, int sAlpha,
    const float* __restrict__ rel) {
    const int z = blockIdx.z;
    A += z * sA; B += z * sB; C += z * sC;
    if (MODE == 2 || MODE == 3) aux += z * sAux;
    if (MODE == 4) bias += (long)z * LL;
    const float* alpha = (MODE == 3) ? (alphaP + (long)z * sAlpha) : nullptr;

    __shared__ unsigned As[2][16][132];
    __shared__ unsigned Bs[2][16][132];

    const int tid  = threadIdx.x;
    const int wid  = tid >> 5, lane = tid & 31;
    const int gid  = lane >> 2, tig = lane & 3;
    const int wm   = wid & 1, wn = wid >> 1;
    const int m0   = blockIdx.y * 128, n0 = blockIdx.x * 128;

    const int a_r = tid >> 2, a_c = (tid & 3) << 2;     // A & transB loads
    const int b_r = tid >> 5, b_c = (tid & 31) << 2;    // row-major B loads

    float4 ra0, ra1, rb0, rb1;
    float acc[4][4][4] = {};

    // ---- prologue load tile 0
    {
        int k0 = 0;
        ra0 = *(const float4*)(A + (long)(m0 + a_r) * lda + k0 + a_c);
        ra1 = *(const float4*)(A + (long)(m0 + a_r + 64) * lda + k0 + a_c);
        if (TRANSB) {
            rb0 = *(const float4*)(B + (long)(n0 + a_r) * ldb + k0 + a_c);
            rb1 = *(const float4*)(B + (long)(n0 + a_r + 64) * ldb + k0 + a_c);
        } else {
            rb0 = *(const float4*)(B + (long)(k0 + b_r) * ldb + n0 + b_c);
            rb1 = *(const float4*)(B + (long)(k0 + b_r + 8) * ldb + n0 + b_c);
        }
        As[0][a_c + 0][a_r] = f2tf32(ra0.x); As[0][a_c + 1][a_r] = f2tf32(ra0.y);
        As[0][a_c + 2][a_r] = f2tf32(ra0.z); As[0][a_c + 3][a_r] = f2tf32(ra0.w);
        As[0][a_c + 0][a_r + 64] = f2tf32(ra1.x); As[0][a_c + 1][a_r + 64] = f2tf32(ra1.y);
        As[0][a_c + 2][a_r + 64] = f2tf32(ra1.z); As[0][a_c + 3][a_r + 64] = f2tf32(ra1.w);
        if (TRANSB) {
            Bs[0][a_c + 0][a_r] = f2tf32(rb0.x); Bs[0][a_c + 1][a_r] = f2tf32(rb0.y);
            Bs[0][a_c + 2][a_r] = f2tf32(rb0.z); Bs[0][a_c + 3][a_r] = f2tf32(rb0.w);
            Bs[0][a_c + 0][a_r + 64] = f2tf32(rb1.x); Bs[0][a_c + 1][a_r + 64] = f2tf32(rb1.y);
            Bs[0][a_c + 2][a_r + 64] = f2tf32(rb1.z); Bs[0][a_c + 3][a_r + 64] = f2tf32(rb1.w);
        } else {
            Bs[0][b_r][b_c + 0] = f2tf32(rb0.x); Bs[0][b_r][b_c + 1] = f2tf32(rb0.y);
            Bs[0][b_r][b_c + 2] = f2tf32(rb0.z); Bs[0][b_r][b_c + 3] = f2tf32(rb0.w);
            Bs[0][b_r + 8][b_c + 0] = f2tf32(rb1.x); Bs[0][b_r + 8][b_c + 1] = f2tf32(rb1.y);
            Bs[0][b_r + 8][b_c + 2] = f2tf32(rb1.z); Bs[0][b_r + 8][b_c + 3] = f2tf32(rb1.w);
        }
    }
    __syncthreads();

    int cur = 0;
    for (int k0 = 0; k0 < K; k0 += 16) {
        const bool nxt = (k0 + 16) < K;
        if (nxt) {
            int kn = k0 + 16;
            ra0 = *(const float4*)(A + (long)(m0 + a_r) * lda + kn + a_c);
            ra1 = *(const float4*)(A + (long)(m0 + a_r + 64) * lda + kn + a_c);
            if (TRANSB) {
                rb0 = *(const float4*)(B + (long)(n0 + a_r) * ldb + kn + a_c);
                rb1 = *(const float4*)(B + (long)(n0 + a_r + 64) * ldb + kn + a_c);
            } else {
                rb0 = *(const float4*)(B + (long)(kn + b_r) * ldb + n0 + b_c);
                rb1 = *(const float4*)(B + (long)(kn + b_r + 8) * ldb + n0 + b_c);
            }
        }
        #pragma unroll
        for (int ks = 0; ks < 16; ks += 8) {
            unsigned af[4][4], bf[4][2];
            #pragma unroll
            for (int mi = 0; mi < 4; mi++) {
                int r = wm * 64 + mi * 16 + gid;
                af[mi][0] = As[cur][ks + tig][r];
                af[mi][1] = As[cur][ks + tig][r + 8];
                af[mi][2] = As[cur][ks + tig + 4][r];
                af[mi][3] = As[cur][ks + tig + 4][r + 8];
            }
            #pragma unroll
            for (int ni = 0; ni < 4; ni++) {
                int cn = wn * 32 + ni * 8 + gid;
                bf[ni][0] = Bs[cur][ks + tig][cn];
                bf[ni][1] = Bs[cur][ks + tig + 4][cn];
            }
            #pragma unroll
            for (int mi = 0; mi < 4; mi++)
                #pragma unroll
                for (int ni = 0; ni < 4; ni++)
                    mma_tf32(acc[mi][ni], af[mi], bf[ni]);
        }
        if (nxt) {
            int nb = cur ^ 1;
            As[nb][a_c + 0][a_r] = f2tf32(ra0.x); As[nb][a_c + 1][a_r] = f2tf32(ra0.y);
            As[nb][a_c + 2][a_r] = f2tf32(ra0.z); As[nb][a_c + 3][a_r] = f2tf32(ra0.w);
            As[nb][a_c + 0][a_r + 64] = f2tf32(ra1.x); As[nb][a_c + 1][a_r + 64] = f2tf32(ra1.y);
            As[nb][a_c + 2][a_r + 64] = f2tf32(ra1.z); As[nb][a_c + 3][a_r + 64] = f2tf32(ra1.w);
            if (TRANSB) {
                Bs[nb][a_c + 0][a_r] = f2tf32(rb0.x); Bs[nb][a_c + 1][a_r] = f2tf32(rb0.y);
                Bs[nb][a_c + 2][a_r] = f2tf32(rb0.z); Bs[nb][a_c + 3][a_r] = f2tf32(rb0.w);
                Bs[nb][a_c + 0][a_r + 64] = f2tf32(rb1.x); Bs[nb][a_c + 1][a_r + 64] = f2tf32(rb1.y);
                Bs[nb][a_c + 2][a_r + 64] = f2tf32(rb1.z); Bs[nb][a_c + 3][a_r + 64] = f2tf32(rb1.w);
            } else {
                Bs[nb][b_r][b_c + 0] = f2tf32(rb0.x); Bs[nb][b_r][b_c + 1] = f2tf32(rb0.y);
                Bs[nb][b_r][b_c + 2] = f2tf32(rb0.z); Bs[nb][b_r][b_c + 3] = f2tf32(rb0.w);
                Bs[nb][b_r + 8][b_c + 0] = f2tf32(rb1.x); Bs[nb][b_r + 8][b_c + 1] = f2tf32(rb1.y);
                Bs[nb][b_r + 8][b_c + 2] = f2tf32(rb1.z); Bs[nb][b_r + 8][b_c + 3] = f2tf32(rb1.w);
            }
            __syncthreads();
        }
        cur ^= 1;
    }

    // ---- epilogue
    #pragma unroll
    for (int mi = 0; mi < 4; mi++) {
        #pragma unroll
        for (int half = 0; half < 2; half++) {
            long r = m0 + wm * 64 + mi * 16 + gid + half * 8;
            #pragma unroll
            for (int ni = 0; ni < 4; ni++) {
                int c = n0 + wn * 32 + ni * 8 + tig * 2;
                float v0 = acc[mi][ni][half * 2 + 0];
                float v1 = acc[mi][ni][half * 2 + 1];
                if (MODE == 1) {
                    v0 = siluf(v0 + bias[c]); v1 = siluf(v1 + bias[c + 1]);
                } else if (MODE == 2) {
                    const float2 g = *(const float2*)(aux + r * (long)ldaux + c);
                    v0 *= g.x; v1 *= g.y;
                } else if (MODE == 3) {
                    const float2 sres = *(const float2*)(aux + r * (long)ldaux + c);
                    v0 = (v0 + bias[c]) * (1.f + alpha[c]) + sres.x;
                    v1 = (v1 + bias[c + 1]) * (1.f + alpha[c + 1]) + sres.y;
                } else if (MODE == 4) {
                    int d0 = (int)r - c;     d0 = d0 < -64 ? -64 : (d0 > 64 ? 64 : d0);
                    int d1 = (int)r - c - 1; d1 = d1 < -64 ? -64 : (d1 > 64 ? 64 : d1);
                    v0 += bias[c] + rel[d0 + 64];
                    v1 += bias[c + 1] + rel[d1 + 64];
                }
                *(float2*)(C + r * (long)ldc + c) = make_float2(v0, v1);
            }
        }
    }
}

// ---------------- q/k build + RoPE (q pre-scaled by qk_scaling) -------------
__global__ void qk_rope_k(const float* __restrict__ h, const float* __restrict__ mw,
                          const float* __restrict__ mb, const float* __restrict__ scal,
                          float* __restrict__ q, float* __restrict__ k) {
    const int row = blockIdx.x;
    const int t   = threadIdx.x;           // 0..127
    const int pos = row & (LL - 1);
    const float* base = h + (long)row * GVA_N + 2 * PROJ;
    float b0 = base[t], b1 = base[t + 128];
    float q0 = fmaf(b0, mw[t],       mb[t]);
    float q1 = fmaf(b1, mw[t + 128], mb[t + 128]);
    float k0 = fmaf(b0, mw[256 + t],       mb[256 + t]);
    float k1 = fmaf(b1, mw[256 + t + 128], mb[256 + t + 128]);
    float freq = exp2f(-(float)t * (13.287712379549449f / 128.f));
    float ang = (float)pos * freq;
    float sn, cs; sincosf(ang, &sn, &cs);
    float sc = scal[row];
    q[(long)row * 256 + t]       = (q0 * cs - q1 * sn) * sc;
    q[(long)row * 256 + t + 128] = (q1 * cs + q0 * sn) * sc;
    k[(long)row * 256 + t]       =  k0 * cs - k1 * sn;
    k[(long)row * 256 + t + 128] =  k1 * cs + k0 * sn;
}

// ---------------- row softmax over 1024 --------------------------------------
__global__ __launch_bounds__(256) void softmax_k(float* __restrict__ S) {
    float4* p = (float4*)(S + (long)blockIdx.x * LL);
    float4 v = p[threadIdx.x];
    __shared__ float rm[8], rs[8];
    float m = fmaxf(fmaxf(v.x, v.y), fmaxf(v.z, v.w));
    m = warpMax(m);
    if ((threadIdx.x & 31) == 0) rm[threadIdx.x >> 5] = m;
    __syncthreads();
    m = rm[0];
    #pragma unroll
    for (int i = 1; i < 8; i++) m = fmaxf(m, rm[i]);
    v.x = __expf(v.x - m); v.y = __expf(v.y - m);
    v.z = __expf(v.z - m); v.w = __expf(v.w - m);
    float s = v.x + v.y + v.z + v.w;
    s = warpSum(s);
    if ((threadIdx.x & 31) == 0) rs[threadIdx.x >> 5] = s;
    __syncthreads();
    s = 0.f;
    #pragma unroll
    for (int i = 0; i < 8; i++) s += rs[i];
    float inv = 1.f / s;
    v.x *= inv; v.y *= inv; v.z *= inv; v.w *= inv;
    p[threadIdx.x] = v;
}

// ---------------- edge = attn[0] + attn[1] -----------------------------------
__global__ void edge_k(const float* __restrict__ attn, float* __restrict__ e) {
    long i = (long)blockIdx.x * 256 + threadIdx.x;
    float4 a = ((const float4*)attn)[i];
    float4 b = ((const float4*)(attn + (long)LL * LL))[i];
    ((float4*)e)[i] = make_float4(a.x + b.x, a.y + b.y, a.z + b.z, a.w + b.w);
}

// ---------------- launch ------------------------------------------------------
extern "C" void kernel_launch(void* const* d_in, const int* in_sizes, int n_in,
                              void* d_out, int out_size) {
    const float* node      = (const float*)d_in[0];
    const float* qk_scal   = (const float*)d_in[1];
    const float* bias      = (const float*)d_in[2];
    const float* cond      = (const float*)d_in[3];
    const float* w_gva     = (const float*)d_in[4];
    const float* b_gva     = (const float*)d_in[5];
    const float* mhs_w     = (const float*)d_in[6];
    const float* mhs_b     = (const float*)d_in[7];
    const float* relpos    = (const float*)d_in[8];
    const float* w_out     = (const float*)d_in[9];
    const float* b_out     = (const float*)d_in[10];
    const float* w_adaln   = (const float*)d_in[11];
    const float* b_adaln   = (const float*)d_in[12];
    float* out = (float*)d_out;

    float *sc, *part, *gba, *x, *h, *q, *k, *attn, *av, *nodeb;
    cudaGetSymbolAddress((void**)&sc,    d_sc);
    cudaGetSymbolAddress((void**)&part,  d_part);
    cudaGetSymbolAddress((void**)&gba,   d_gba);
    cudaGetSymbolAddress((void**)&x,     d_x);
    cudaGetSymbolAddress((void**)&h,     d_h);
    cudaGetSymbolAddress((void**)&q,     d_q);
    cudaGetSymbolAddress((void**)&k,     d_k);
    cudaGetSymbolAddress((void**)&attn,  d_attn);
    cudaGetSymbolAddress((void**)&av,    d_av);
    cudaGetSymbolAddress((void**)&nodeb, d_node);

    cudaMemcpyAsync(nodeb, node, (size_t)ROWS * NODE * sizeof(float),
                    cudaMemcpyDeviceToDevice);
    silu_vec_k<<<(BB * NODE + 255) / 256, 256>>>(cond, sc, BB * NODE);

    // adaLN for all layers up front (cond is layer-invariant)
    adaln_part_k<<<dim3(ADALN_N / 256, BB * KSLICE, NL), 256>>>(sc, w_adaln, part);
    adaln_reduce_k<<<(NL * BB * ADALN_N) / 256, 256>>>(part, b_adaln, gba);

    for (int l = 0; l < NL; l++) {
        const float* gba_l = gba + (long)l * BB * ADALN_N;

        ln_mod_k<<<ROWS, 256>>>(nodeb, gba_l, x);

        // h = silu(x @ w_gva + b_gva)
        tgemm_k<1, false><<<dim3(GVA_N / 128, LL / 128, BB), 256>>>(
            NODE,
            x, NODE, (long)LL * NODE,
            w_gva + (long)l * NODE * GVA_N, GVA_N, 0L,
            h, GVA_N, (long)LL * GVA_N,
            b_gva + l * GVA_N,
            nullptr, 0, 0L, nullptr, 0, nullptr);

        qk_rope_k<<<ROWS, 128>>>(h, mhs_w + l * 2 * ATTND, mhs_b + l * 2 * ATTND,
                                 qk_scal, q, k);

        // logits = q @ k^T + bias + rel
        tgemm_k<4, true><<<dim3(LL / 128, LL / 128, BB), 256>>>(
            ATTND,
            q, ATTND, (long)LL * ATTND,
            k, ATTND, (long)LL * ATTND,
            attn, LL, (long)LL * LL,
            bias,
            nullptr, 0, 0L, nullptr, 0,
            relpos + l * NREL);

        softmax_k<<<ROWS, 256>>>(attn);

        if (l == NL - 1)
            edge_k<<<(LL * LL / 4) / 256, 256>>>(attn, out + (long)ROWS * NODE);

        // av = (attn @ values) * gates
        tgemm_k<2, false><<<dim3(PROJ / 128, LL / 128, BB), 256>>>(
            LL,
            attn, LL, (long)LL * LL,
            h + PROJ, GVA_N, (long)LL * GVA_N,
            av, PROJ, (long)LL * PROJ,
            nullptr,
            h, GVA_N, (long)LL * GVA_N,
            nullptr, 0, nullptr);

        // node = (av @ w_out + b_out)*(1+alpha) + shortcut
        float* Cdst = (l == NL - 1) ? out : nodeb;
        tgemm_k<3, false><<<dim3(NODE / 128, LL / 128, BB), 256>>>(
            PROJ,
            av, PROJ, (long)LL * PROJ,
            w_out + (long)l * PROJ * NODE, NODE, 0L,
            Cdst, NODE, (long)LL * NODE,
            b_out + l * NODE,
            nodeb, NODE, (long)LL * NODE,
            gba_l + 2 * NODE, ADALN_N, nullptr);
    }
    (void)in_sizes; (void)n_in; (void)out_size;
}

// round 5
// speedup vs baseline: 3.5726x; 1.2964x over previous
#include <cuda_runtime.h>
#include <cuda_bf16.h>
#include <cstdint>
#include <math.h>

#define NODE   1280
#define PROJ   2560
#define ATTND  256
#define NREL   129
#define NL     4
#define BB     2
#define LL     1024
#define GVA_N  (2*PROJ + ATTND)   // 5376
#define ADALN_N (3*NODE)          // 3840
#define ROWS   (BB*LL)            // 2048
#define KSLICE 4

// ---------------- scratch (device globals; no allocation allowed) ----------
__device__ float d_sc   [BB*NODE];
__device__ float d_part [NL*BB*KSLICE*ADALN_N];
__device__ float d_gba  [NL*BB*ADALN_N];
__device__ float d_x    [ROWS*NODE];
__device__ float d_h    [ROWS*GVA_N];
__device__ float d_q    [ROWS*ATTND];
__device__ float d_k    [ROWS*ATTND];
__device__ float d_attn [(long)BB*LL*LL];
__device__ float d_av   [ROWS*PROJ];
__device__ float d_node [ROWS*NODE];

// ---------------- helpers ---------------------------------------------------
__device__ __forceinline__ float siluf(float x) { return x / (1.f + __expf(-x)); }
__device__ __forceinline__ float warpMax(float v) {
    #pragma unroll
    for (int o = 16; o > 0; o >>= 1) v = fmaxf(v, __shfl_xor_sync(0xffffffffu, v, o));
    return v;
}
__device__ __forceinline__ float warpSum(float v) {
    #pragma unroll
    for (int o = 16; o > 0; o >>= 1) v += __shfl_xor_sync(0xffffffffu, v, o);
    return v;
}
__device__ __forceinline__ unsigned f2tf32(float f) {
    unsigned u; asm("cvt.rna.tf32.f32 %0, %1;" : "=r"(u) : "f"(f)); return u;
}
__device__ __forceinline__ uint32_t smem_u32(const void* p) {
    uint32_t a;
    asm("{ .reg .u64 t; cvta.to.shared.u64 t, %1; cvt.u32.u64 %0, t; }"
        : "=r"(a) : "l"(p));
    return a;
}
__device__ __forceinline__ void cp16(uint32_t dst, const void* src) {
    asm volatile("cp.async.cg.shared.global [%0], [%1], 16;" :: "r"(dst), "l"(src));
}
__device__ __forceinline__ void cp4(uint32_t dst, const void* src) {
    asm volatile("cp.async.ca.shared.global [%0], [%1], 4;" :: "r"(dst), "l"(src));
}
__device__ __forceinline__ void cp_commit() {
    asm volatile("cp.async.commit_group;" ::: "memory");
}
template <int N>
__device__ __forceinline__ void cp_wait() {
    asm volatile("cp.async.wait_group %0;" :: "n"(N) : "memory");
}
__device__ __forceinline__ void mma_tf32(float* c, const unsigned* a, const unsigned* b) {
    asm volatile(
        "mma.sync.aligned.m16n8k8.row.col.f32.tf32.tf32.f32 "
        "{%0,%1,%2,%3}, {%4,%5,%6,%7}, {%8,%9}, {%0,%1,%2,%3};"
        : "+f"(c[0]), "+f"(c[1]), "+f"(c[2]), "+f"(c[3])
        : "r"(a[0]), "r"(a[1]), "r"(a[2]), "r"(a[3]), "r"(b[0]), "r"(b[1]));
}

// ---------------- silu(cond) -------------------------------------------------
__global__ void silu_vec_k(const float* __restrict__ c, float* __restrict__ sc, int n) {
    int i = blockIdx.x * 256 + threadIdx.x;
    if (i < n) sc[i] = siluf(c[i]);
}

// ---------------- adaLN for ALL layers, split-K ------------------------------
__global__ void adaln_part_k(const float* __restrict__ sc, const float* __restrict__ w,
                             float* __restrict__ part) {
    const int l = blockIdx.z, b = blockIdx.y >> 2, ks = blockIdx.y & 3;
    const int col = blockIdx.x * 256 + threadIdx.x;
    const int KC = NODE / KSLICE;      // 320
    const float* s  = sc + b * NODE + ks * KC;
    const float* wp = w + (long)l * NODE * ADALN_N + (long)ks * KC * ADALN_N + col;
    float acc = 0.f;
    #pragma unroll 8
    for (int k = 0; k < KC; k++)
        acc = fmaf(s[k], wp[(long)k * ADALN_N], acc);
    part[((((long)l * BB) + b) * KSLICE + ks) * ADALN_N + col] = acc;
}
__global__ void adaln_reduce_k(const float* __restrict__ part,
                               const float* __restrict__ bvec, float* __restrict__ gba) {
    long idx = (long)blockIdx.x * 256 + threadIdx.x;
    int l = (int)(idx / (BB * ADALN_N));
    int rem = (int)(idx % (BB * ADALN_N));
    int b = rem / ADALN_N, col = rem % ADALN_N;
    const float* p = part + (((long)l * BB + b) * KSLICE) * ADALN_N + col;
    gba[idx] = bvec[l * ADALN_N + col] + p[0] + p[ADALN_N] + p[2 * ADALN_N] + p[3 * ADALN_N];
}

// ---------------- LayerNorm + modulate --------------------------------------
__global__ __launch_bounds__(256) void ln_mod_k(const float* __restrict__ node,
                                                const float* __restrict__ gba,
                                                float* __restrict__ x) {
    const int row = blockIdx.x;
    const int b   = row >> 10;
    const float* p = node + (long)row * NODE;
    float vals[5];
    float s = 0.f, sq = 0.f;
    #pragma unroll
    for (int i = 0; i < 5; i++) {
        float v = p[threadIdx.x + i * 256];
        vals[i] = v; s += v; sq += v * v;
    }
    __shared__ float rs[8], rq[8];
    s = warpSum(s); sq = warpSum(sq);
    if ((threadIdx.x & 31) == 0) { rs[threadIdx.x >> 5] = s; rq[threadIdx.x >> 5] = sq; }
    __syncthreads();
    float ts = 0.f, tq = 0.f;
    #pragma unroll
    for (int i = 0; i < 8; i++) { ts += rs[i]; tq += rq[i]; }
    const float mean = ts * (1.f / NODE);
    const float var  = tq * (1.f / NODE) - mean * mean;
    const float rstd = rsqrtf(var + 1e-5f);
    const float* g = gba + (long)b * ADALN_N;
    float* xo = x + (long)row * NODE;
    #pragma unroll
    for (int i = 0; i < 5; i++) {
        int c = threadIdx.x + i * 256;
        float v = (vals[i] - mean) * rstd;
        xo[c] = v * (1.f + g[c]) + g[NODE + c];
    }
}

// ============================================================================
// tf32 mma.sync GEMM, 128x128 tile, 4-stage cp.async pipeline, K=16/stage.
// A: [M,K] row-major fp32. B: BTRANS=false -> [K,N] row-major (weights/values)
//                            BTRANS=true  -> [N,K] row-major (k-matrix)
// SMEM per stage: A [128][20] fp32  +  B [16][136] fp32 (both conflict-free).
// MODE 1: C = silu(acc + bias[n])
// MODE 2: C = acc * aux[m,n]
// MODE 3: C = (acc + bias[n])*(1+alpha[n]) + aux[m,n]
// MODE 4: C = acc + bias[n] + rel[clamp(m-n,-64,64)+64]   (bias per-batch row)
// ============================================================================
#define APAD 20
#define BPAD 136
#define STG_FLT (128*APAD + 16*BPAD)     // 4736 floats
#define SMEMSZ  (4*STG_FLT*4)            // 75776 bytes

template <int MODE, bool BTRANS>
__global__ __launch_bounds__(256, 2) void tgemm2(
    int K,
    const float* __restrict__ A, int lda, long sA,
    const float* __restrict__ B, int ldb, long sB,
    float* __restrict__ C, int ldc, long sC,
    const float* __restrict__ bias,
    const float* __restrict__ aux, int ldaux, long sAux,
    const float* __restrict__ alphaP, int sAlpha,
    const float* __restrict__ rel) {
    extern __shared__ float sm[];
    const int z = blockIdx.z;
    A += z * sA; B += z * sB; C += z * sC;
    if (MODE == 2 || MODE == 3) aux += z * sAux;
    if (MODE == 4) bias += (long)z * LL;
    const float* alpha = (MODE == 3) ? (alphaP + (long)z * sAlpha) : nullptr;

    const int tid = threadIdx.x, wid = tid >> 5, lane = tid & 31;
    const int gid = lane >> 2, tig = lane & 3;
    const int wm = wid & 1, wn = wid >> 1;
    const int m0 = blockIdx.y * 128, n0 = blockIdx.x * 128;
    const uint32_t smb = smem_u32(sm);
    const int nk = K >> 4;

    // ---- stage loader
    auto load_stage = [&](int c) {
        const int slot = c & 3;
        const uint32_t abase = smb + (uint32_t)(slot * STG_FLT) * 4;
        const uint32_t bbase = abase + 128 * APAD * 4;
        // A: 128 x 16 fp32, [m][k] layout
        #pragma unroll
        for (int i = 0; i < 2; i++) {
            int vec = tid + i * 256;
            int r = vec >> 2, c4 = (vec & 3) << 2;
            cp16(abase + (uint32_t)(r * APAD + c4) * 4,
                 A + (long)(m0 + r) * lda + c * 16 + c4);
        }
        if (!BTRANS) {
            // B: 16 x 128 fp32, [k][n] layout, direct row copies
            #pragma unroll
            for (int i = 0; i < 2; i++) {
                int vec = tid + i * 256;
                int r = vec >> 5, c4 = (vec & 31) << 2;
                cp16(bbase + (uint32_t)(r * BPAD + c4) * 4,
                     B + (long)(c * 16 + r) * ldb + n0 + c4);
            }
        } else {
            // B: [N,K] -> transpose into [k][n], 4B copies
            #pragma unroll
            for (int i = 0; i < 8; i++) {
                int e = tid + i * 256;
                int kk = e & 15, n = e >> 4;
                cp4(bbase + (uint32_t)(kk * BPAD + n) * 4,
                    B + (long)(n0 + n) * ldb + c * 16 + kk);
            }
        }
    };

    // ---- prologue: 3 stages in flight
    load_stage(0); cp_commit();
    load_stage(1); cp_commit();
    load_stage(2); cp_commit();

    float acc[4][4][4] = {};
    for (int c = 0; c < nk; c++) {
        cp_wait<2>();
        __syncthreads();
        if (c + 3 < nk) load_stage(c + 3);
        cp_commit();

        const float* As_ = sm + (c & 3) * STG_FLT;
        const float* Bs_ = As_ + 128 * APAD;
        #pragma unroll
        for (int ks = 0; ks < 16; ks += 8) {
            unsigned af[4][4], bf[4][2];
            #pragma unroll
            for (int mi = 0; mi < 4; mi++) {
                int r = wm * 64 + mi * 16 + gid;
                af[mi][0] = f2tf32(As_[r * APAD + ks + tig]);
                af[mi][1] = f2tf32(As_[(r + 8) * APAD + ks + tig]);
                af[mi][2] = f2tf32(As_[r * APAD + ks + tig + 4]);
                af[mi][3] = f2tf32(As_[(r + 8) * APAD + ks + tig + 4]);
            }
            #pragma unroll
            for (int ni = 0; ni < 4; ni++) {
                int cn = wn * 32 + ni * 8 + gid;
                bf[ni][0] = f2tf32(Bs_[(ks + tig) * BPAD + cn]);
                bf[ni][1] = f2tf32(Bs_[(ks + tig + 4) * BPAD + cn]);
            }
            #pragma unroll
            for (int mi = 0; mi < 4; mi++)
                #pragma unroll
                for (int ni = 0; ni < 4; ni++)
                    mma_tf32(acc[mi][ni], af[mi], bf[ni]);
        }
    }

    // ---- epilogue
    #pragma unroll
    for (int mi = 0; mi < 4; mi++) {
        #pragma unroll
        for (int half = 0; half < 2; half++) {
            long r = m0 + wm * 64 + mi * 16 + gid + half * 8;
            #pragma unroll
            for (int ni = 0; ni < 4; ni++) {
                int c = n0 + wn * 32 + ni * 8 + tig * 2;
                float v0 = acc[mi][ni][half * 2 + 0];
                float v1 = acc[mi][ni][half * 2 + 1];
                if (MODE == 1) {
                    v0 = siluf(v0 + bias[c]); v1 = siluf(v1 + bias[c + 1]);
                } else if (MODE == 2) {
                    const float2 g = *(const float2*)(aux + r * (long)ldaux + c);
                    v0 *= g.x; v1 *= g.y;
                } else if (MODE == 3) {
                    const float2 sres = *(const float2*)(aux + r * (long)ldaux + c);
                    v0 = (v0 + bias[c]) * (1.f + alpha[c]) + sres.x;
                    v1 = (v1 + bias[c + 1]) * (1.f + alpha[c + 1]) + sres.y;
                } else if (MODE == 4) {
                    int d0 = (int)r - c;     d0 = d0 < -64 ? -64 : (d0 > 64 ? 64 : d0);
                    int d1 = (int)r - c - 1; d1 = d1 < -64 ? -64 : (d1 > 64 ? 64 : d1);
                    v0 += bias[c] + rel[d0 + 64];
                    v1 += bias[c + 1] + rel[d1 + 64];
                }
                *(float2*)(C + r * (long)ldc + c) = make_float2(v0, v1);
            }
        }
    }
}

// ---------------- q/k build + RoPE (q pre-scaled by qk_scaling) -------------
__global__ void qk_rope_k(const float* __restrict__ h, const float* __restrict__ mw,
                          const float* __restrict__ mb, const float* __restrict__ scal,
                          float* __restrict__ q, float* __restrict__ k) {
    const int row = blockIdx.x;
    const int t   = threadIdx.x;           // 0..127
    const int pos = row & (LL - 1);
    const float* base = h + (long)row * GVA_N + 2 * PROJ;
    float b0 = base[t], b1 = base[t + 128];
    float q0 = fmaf(b0, mw[t],       mb[t]);
    float q1 = fmaf(b1, mw[t + 128], mb[t + 128]);
    float k0 = fmaf(b0, mw[256 + t],       mb[256 + t]);
    float k1 = fmaf(b1, mw[256 + t + 128], mb[256 + t + 128]);
    float freq = exp2f(-(float)t * (13.287712379549449f / 128.f));
    float ang = (float)pos * freq;
    float sn, cs; sincosf(ang, &sn, &cs);
    float sc = scal[row];
    q[(long)row * 256 + t]       = (q0 * cs - q1 * sn) * sc;
    q[(long)row * 256 + t + 128] = (q1 * cs + q0 * sn) * sc;
    k[(long)row * 256 + t]       =  k0 * cs - k1 * sn;
    k[(long)row * 256 + t + 128] =  k1 * cs + k0 * sn;
}

// ---------------- row softmax over 1024 --------------------------------------
__global__ __launch_bounds__(256) void softmax_k(float* __restrict__ S) {
    float4* p = (float4*)(S + (long)blockIdx.x * LL);
    float4 v = p[threadIdx.x];
    __shared__ float rm[8], rs[8];
    float m = fmaxf(fmaxf(v.x, v.y), fmaxf(v.z, v.w));
    m = warpMax(m);
    if ((threadIdx.x & 31) == 0) rm[threadIdx.x >> 5] = m;
    __syncthreads();
    m = rm[0];
    #pragma unroll
    for (int i = 1; i < 8; i++) m = fmaxf(m, rm[i]);
    v.x = __expf(v.x - m); v.y = __expf(v.y - m);
    v.z = __expf(v.z - m); v.w = __expf(v.w - m);
    float s = v.x + v.y + v.z + v.w;
    s = warpSum(s);
    if ((threadIdx.x & 31) == 0) rs[threadIdx.x >> 5] = s;
    __syncthreads();
    s = 0.f;
    #pragma unroll
    for (int i = 0; i < 8; i++) s += rs[i];
    float inv = 1.f / s;
    v.x *= inv; v.y *= inv; v.z *= inv; v.w *= inv;
    p[threadIdx.x] = v;
}

// ---------------- edge = attn[0] + attn[1] -----------------------------------
__global__ void edge_k(const float* __restrict__ attn, float* __restrict__ e) {
    long i = (long)blockIdx.x * 256 + threadIdx.x;
    float4 a = ((const float4*)attn)[i];
    float4 b = ((const float4*)(attn + (long)LL * LL))[i];
    ((float4*)e)[i] = make_float4(a.x + b.x, a.y + b.y, a.z + b.z, a.w + b.w);
}

// ---------------- launch ------------------------------------------------------
extern "C" void kernel_launch(void* const* d_in, const int* in_sizes, int n_in,
                              void* d_out, int out_size) {
    const float* node      = (const float*)d_in[0];
    const float* qk_scal   = (const float*)d_in[1];
    const float* bias      = (const float*)d_in[2];
    const float* cond      = (const float*)d_in[3];
    const float* w_gva     = (const float*)d_in[4];
    const float* b_gva     = (const float*)d_in[5];
    const float* mhs_w     = (const float*)d_in[6];
    const float* mhs_b     = (const float*)d_in[7];
    const float* relpos    = (const float*)d_in[8];
    const float* w_out     = (const float*)d_in[9];
    const float* b_out     = (const float*)d_in[10];
    const float* w_adaln   = (const float*)d_in[11];
    const float* b_adaln   = (const float*)d_in[12];
    float* out = (float*)d_out;

    float *sc, *part, *gba, *x, *h, *q, *k, *attn, *av, *nodeb;
    cudaGetSymbolAddress((void**)&sc,    d_sc);
    cudaGetSymbolAddress((void**)&part,  d_part);
    cudaGetSymbolAddress((void**)&gba,   d_gba);
    cudaGetSymbolAddress((void**)&x,     d_x);
    cudaGetSymbolAddress((void**)&h,     d_h);
    cudaGetSymbolAddress((void**)&q,     d_q);
    cudaGetSymbolAddress((void**)&k,     d_k);
    cudaGetSymbolAddress((void**)&attn,  d_attn);
    cudaGetSymbolAddress((void**)&av,    d_av);
    cudaGetSymbolAddress((void**)&nodeb, d_node);

    cudaFuncSetAttribute(tgemm2<1, false>,
                         cudaFuncAttributeMaxDynamicSharedMemorySize, SMEMSZ);
    cudaFuncSetAttribute(tgemm2<2, false>,
                         cudaFuncAttributeMaxDynamicSharedMemorySize, SMEMSZ);
    cudaFuncSetAttribute(tgemm2<3, false>,
                         cudaFuncAttributeMaxDynamicSharedMemorySize, SMEMSZ);
    cudaFuncSetAttribute(tgemm2<4, true>,
                         cudaFuncAttributeMaxDynamicSharedMemorySize, SMEMSZ);

    cudaMemcpyAsync(nodeb, node, (size_t)ROWS * NODE * sizeof(float),
                    cudaMemcpyDeviceToDevice);
    silu_vec_k<<<(BB * NODE + 255) / 256, 256>>>(cond, sc, BB * NODE);
    adaln_part_k<<<dim3(ADALN_N / 256, BB * KSLICE, NL), 256>>>(sc, w_adaln, part);
    adaln_reduce_k<<<(NL * BB * ADALN_N) / 256, 256>>>(part, b_adaln, gba);

    for (int l = 0; l < NL; l++) {
        const float* gba_l = gba + (long)l * BB * ADALN_N;

        ln_mod_k<<<ROWS, 256>>>(nodeb, gba_l, x);

        // h = silu(x @ w_gva + b_gva)   [2048 x 5376 x 1280]
        tgemm2<1, false><<<dim3(GVA_N / 128, ROWS / 128, 1), 256, SMEMSZ>>>(
            NODE,
            x, NODE, 0L,
            w_gva + (long)l * NODE * GVA_N, GVA_N, 0L,
            h, GVA_N, 0L,
            b_gva + l * GVA_N,
            nullptr, 0, 0L, nullptr, 0, nullptr);

        qk_rope_k<<<ROWS, 128>>>(h, mhs_w + l * 2 * ATTND, mhs_b + l * 2 * ATTND,
                                 qk_scal, q, k);

        // logits = q @ k^T + bias + rel   [1024 x 1024 x 256] x2
        tgemm2<4, true><<<dim3(LL / 128, LL / 128, BB), 256, SMEMSZ>>>(
            ATTND,
            q, ATTND, (long)LL * ATTND,
            k, ATTND, (long)LL * ATTND,
            attn, LL, (long)LL * LL,
            bias,
            nullptr, 0, 0L, nullptr, 0,
            relpos + l * NREL);

        softmax_k<<<ROWS, 256>>>(attn);

        if (l == NL - 1)
            edge_k<<<(LL * LL / 4) / 256, 256>>>(attn, out + (long)ROWS * NODE);

        // av = (attn @ values) * gates   [1024 x 2560 x 1024] x2
        tgemm2<2, false><<<dim3(PROJ / 128, LL / 128, BB), 256, SMEMSZ>>>(
            LL,
            attn, LL, (long)LL * LL,
            h + PROJ, GVA_N, (long)LL * GVA_N,
            av, PROJ, (long)LL * PROJ,
            nullptr,
            h, GVA_N, (long)LL * GVA_N,
            nullptr, 0, nullptr);

        // node = (av @ w_out + b_out)*(1+alpha) + shortcut  [1024 x 1280 x 2560] x2
        float* Cdst = (l == NL - 1) ? out : nodeb;
        tgemm2<3, false><<<dim3(NODE / 128, LL / 128, BB), 256, SMEMSZ>>>(
            PROJ,
            av, PROJ, (long)LL * PROJ,
            w_out + (long)l * PROJ * NODE, NODE, 0L,
            Cdst, NODE, (long)LL * NODE,
            b_out + l * NODE,
            nodeb, NODE, (long)LL * NODE,
            gba_l + 2 * NODE, ADALN_N, nullptr);
    }
    (void)in_sizes; (void)n_in; (void)out_size;
}

// round 6
// speedup vs baseline: 7.1829x; 2.0106x over previous
#include <cuda_runtime.h>
#include <cuda_fp16.h>
#include <cstdint>
#include <math.h>

#define NODE   1280
#define PROJ   2560
#define ATTND  256
#define NREL   129
#define NL     4
#define BB     2
#define LL     1024
#define GVA_N  (2*PROJ + ATTND)   // 5376
#define ADALN_N (3*NODE)          // 3840
#define ROWS   (BB*LL)            // 2048
#define KSLICE 4

// ---------------- scratch (device globals; no allocation allowed) ----------
__device__ float  d_sc    [BB*NODE];
__device__ float  d_part  [NL*BB*KSLICE*ADALN_N];
__device__ float  d_gba   [NL*BB*ADALN_N];
__device__ __half d_x16   [ROWS*NODE];
__device__ float  d_h     [ROWS*GVA_N];
__device__ __half d_h16   [ROWS*GVA_N];
__device__ __half d_q16   [ROWS*ATTND];
__device__ __half d_k16   [ROWS*ATTND];
__device__ float  d_attn  [(long)BB*LL*LL];
__device__ __half d_attn16[(long)BB*LL*LL];
__device__ __half d_av16  [ROWS*PROJ];
__device__ float  d_node  [ROWS*NODE];
__device__ __half d_wgva16[(long)NL*NODE*GVA_N];
__device__ __half d_wout16[(long)NL*PROJ*NODE];

// ---------------- helpers ---------------------------------------------------
__device__ __forceinline__ float siluf(float x) { return x / (1.f + __expf(-x)); }
__device__ __forceinline__ float warpMax(float v) {
    #pragma unroll
    for (int o = 16; o > 0; o >>= 1) v = fmaxf(v, __shfl_xor_sync(0xffffffffu, v, o));
    return v;
}
__device__ __forceinline__ float warpSum(float v) {
    #pragma unroll
    for (int o = 16; o > 0; o >>= 1) v += __shfl_xor_sync(0xffffffffu, v, o);
    return v;
}
__device__ __forceinline__ uint32_t smem_u32(const void* p) {
    uint32_t a;
    asm("{ .reg .u64 t; cvta.to.shared.u64 t, %1; cvt.u32.u64 %0, t; }"
        : "=r"(a) : "l"(p));
    return a;
}
__device__ __forceinline__ void cp16(uint32_t dst, const void* src) {
    asm volatile("cp.async.cg.shared.global [%0], [%1], 16;" :: "r"(dst), "l"(src));
}
__device__ __forceinline__ void cp_commit() {
    asm volatile("cp.async.commit_group;" ::: "memory");
}
template <int N>
__device__ __forceinline__ void cp_wait() {
    asm volatile("cp.async.wait_group %0;" :: "n"(N) : "memory");
}
__device__ __forceinline__ void ldm_x4(uint32_t* r, uint32_t a) {
    asm volatile("ldmatrix.sync.aligned.m8n8.x4.shared.b16 {%0,%1,%2,%3}, [%4];"
                 : "=r"(r[0]), "=r"(r[1]), "=r"(r[2]), "=r"(r[3]) : "r"(a));
}
__device__ __forceinline__ void ldm_x4_t(uint32_t* r, uint32_t a) {
    asm volatile("ldmatrix.sync.aligned.m8n8.x4.trans.shared.b16 {%0,%1,%2,%3}, [%4];"
                 : "=r"(r[0]), "=r"(r[1]), "=r"(r[2]), "=r"(r[3]) : "r"(a));
}
__device__ __forceinline__ void mma16816(float* c, const uint32_t* a, const uint32_t* b) {
    asm volatile(
        "mma.sync.aligned.m16n8k16.row.col.f32.f16.f16.f32 "
        "{%0,%1,%2,%3}, {%4,%5,%6,%7}, {%8,%9}, {%0,%1,%2,%3};"
        : "+f"(c[0]), "+f"(c[1]), "+f"(c[2]), "+f"(c[3])
        : "r"(a[0]), "r"(a[1]), "r"(a[2]), "r"(a[3]), "r"(b[0]), "r"(b[1]));
}

// ---------------- small kernels ---------------------------------------------
__global__ void silu_vec_k(const float* __restrict__ c, float* __restrict__ sc, int n) {
    int i = blockIdx.x * 256 + threadIdx.x;
    if (i < n) sc[i] = siluf(c[i]);
}

__global__ void f2h_k(const float* __restrict__ in, __half* __restrict__ out) {
    long i = (long)blockIdx.x * 256 + threadIdx.x;
    float4 v = ((const float4*)in)[i];
    ((__half2*)out)[2 * i]     = __floats2half2_rn(v.x, v.y);
    ((__half2*)out)[2 * i + 1] = __floats2half2_rn(v.z, v.w);
}

__global__ void adaln_part_k(const float* __restrict__ sc, const float* __restrict__ w,
                             float* __restrict__ part) {
    const int l = blockIdx.z, b = blockIdx.y >> 2, ks = blockIdx.y & 3;
    const int col = blockIdx.x * 256 + threadIdx.x;
    const int KC = NODE / KSLICE;
    const float* s  = sc + b * NODE + ks * KC;
    const float* wp = w + (long)l * NODE * ADALN_N + (long)ks * KC * ADALN_N + col;
    float acc = 0.f;
    #pragma unroll 8
    for (int k = 0; k < KC; k++)
        acc = fmaf(s[k], wp[(long)k * ADALN_N], acc);
    part[((((long)l * BB) + b) * KSLICE + ks) * ADALN_N + col] = acc;
}
__global__ void adaln_reduce_k(const float* __restrict__ part,
                               const float* __restrict__ bvec, float* __restrict__ gba) {
    long idx = (long)blockIdx.x * 256 + threadIdx.x;
    int l = (int)(idx / (BB * ADALN_N));
    int rem = (int)(idx % (BB * ADALN_N));
    int b = rem / ADALN_N, col = rem % ADALN_N;
    const float* p = part + (((long)l * BB + b) * KSLICE) * ADALN_N + col;
    gba[idx] = bvec[l * ADALN_N + col] + p[0] + p[ADALN_N] + p[2 * ADALN_N] + p[3 * ADALN_N];
}

// LayerNorm + modulate -> fp16 x
__global__ __launch_bounds__(256) void ln_mod_k(const float* __restrict__ node,
                                                const float* __restrict__ gba,
                                                __half* __restrict__ x16) {
    const int row = blockIdx.x;
    const int b   = row >> 10;
    const float* p = node + (long)row * NODE;
    float vals[5];
    float s = 0.f, sq = 0.f;
    #pragma unroll
    for (int i = 0; i < 5; i++) {
        float v = p[threadIdx.x + i * 256];
        vals[i] = v; s += v; sq += v * v;
    }
    __shared__ float rs[8], rq[8];
    s = warpSum(s); sq = warpSum(sq);
    if ((threadIdx.x & 31) == 0) { rs[threadIdx.x >> 5] = s; rq[threadIdx.x >> 5] = sq; }
    __syncthreads();
    float ts = 0.f, tq = 0.f;
    #pragma unroll
    for (int i = 0; i < 8; i++) { ts += rs[i]; tq += rq[i]; }
    const float mean = ts * (1.f / NODE);
    const float var  = tq * (1.f / NODE) - mean * mean;
    const float rstd = rsqrtf(var + 1e-5f);
    const float* g = gba + (long)b * ADALN_N;
    __half* xo = x16 + (long)row * NODE;
    #pragma unroll
    for (int i = 0; i < 5; i++) {
        int c = threadIdx.x + i * 256;
        float v = (vals[i] - mean) * rstd;
        xo[c] = __float2half_rn(v * (1.f + g[c]) + g[NODE + c]);
    }
}

// ============================================================================
// fp16 mma.sync GEMM, 128x128 tile, BK=32, 4-stage cp.async, ldmatrix frags.
// A: fp16 [M,K] row-major.
// B: BKM=false -> fp16 [K,N] row-major (weights/values); SMEM [k][n], ldmatrix.trans
//    BKM=true  -> fp16 [N,K] row-major (k-matrix);      SMEM [n][k], ldmatrix
// MODE 1: C=silu(acc+bias[n]) -> fp32 C + fp16 CH
// MODE 2: (acc * aux[m,n])    -> fp16 CH only
// MODE 3: (acc+bias)*(1+alpha)+aux -> fp32 C
// MODE 4: acc + bias[z,n] + rel[clamp(m-n)] -> fp32 C
// ============================================================================
#define AST 40              // A row stride (halfs)
#define ASZ (128*AST)       // 5120 halfs

template <int MODE, bool BKM>
__global__ __launch_bounds__(256, 2) void hgemm(
    int K,
    const __half* __restrict__ A, int lda, long sA,
    const __half* __restrict__ B, int ldb, long sB,
    float* __restrict__ C, int ldc, long sC,
    __half* __restrict__ CH, int ldch, long sCh,
    const float* __restrict__ bias,
    const float* __restrict__ aux, int ldaux, long sAux,
    const float* __restrict__ alphaP, int sAlpha,
    const float* __restrict__ rel) {
    constexpr int BST = BKM ? 40 : 136;
    constexpr int BSZ = BKM ? 128 * 40 : 32 * 136;
    constexpr int STG = ASZ + BSZ;                 // halfs per stage

    extern __shared__ __half sh[];
    const int z = blockIdx.z;
    A += z * sA; B += z * sB;
    if (MODE == 1 || MODE == 3 || MODE == 4) C += z * sC;
    if (MODE == 1 || MODE == 2) CH += z * sCh;
    if (MODE == 2 || MODE == 3) aux += z * sAux;
    if (MODE == 4) bias += (long)z * LL;
    const float* alpha = (MODE == 3) ? (alphaP + (long)z * sAlpha) : nullptr;

    const int tid = threadIdx.x, wid = tid >> 5, lane = tid & 31;
    const int wm = wid & 1, wn = wid >> 1;
    const int m0 = blockIdx.y * 128, n0 = blockIdx.x * 128;
    const uint32_t smb = smem_u32(sh);
    const int nk = K >> 5;

    // ---- ldmatrix base addresses (stage 0, k=0), bytes
    uint32_t aAddr[4], bAddr[2];
    #pragma unroll
    for (int mi = 0; mi < 4; mi++) {
        int off = (wm * 64 + mi * 16 + (lane & 15)) * AST + ((lane >> 4) << 3);
        aAddr[mi] = smb + off * 2;
    }
    #pragma unroll
    for (int p = 0; p < 2; p++) {
        int off;
        if (BKM) // SMEM [n][k]
            off = (wn * 32 + p * 16 + (lane & 7) + ((lane >> 4) << 3)) * BST
                  + (((lane >> 3) & 1) << 3);
        else     // SMEM [k][n]
            off = (lane & 15) * BST + wn * 32 + p * 16 + ((lane >> 4) << 3);
        bAddr[p] = smb + (ASZ + off) * 2;
    }

    // ---- stage loader (all cp.async, data already fp16)
    auto load_stage = [&](int c) {
        const int slot = c & 3;
        const uint32_t ab = smb + (uint32_t)(slot * STG) * 2;
        const uint32_t bb = ab + ASZ * 2;
        #pragma unroll
        for (int i = 0; i < 2; i++) {           // A: 128 x 32 halfs
            int v = tid + i * 256;
            int r = v >> 2, ch = v & 3;
            cp16(ab + (uint32_t)(r * AST + ch * 8) * 2,
                 A + (long)(m0 + r) * lda + c * 32 + ch * 8);
        }
        if (BKM) {
            #pragma unroll
            for (int i = 0; i < 2; i++) {       // B: 128 n-rows x 32 halfs
                int v = tid + i * 256;
                int r = v >> 2, ch = v & 3;
                cp16(bb + (uint32_t)(r * BST + ch * 8) * 2,
                     B + (long)(n0 + r) * ldb + c * 32 + ch * 8);
            }
        } else {
            #pragma unroll
            for (int i = 0; i < 2; i++) {       // B: 32 k-rows x 128 halfs
                int v = tid + i * 256;
                int r = v >> 4, ch = v & 15;
                cp16(bb + (uint32_t)(r * BST + ch * 8) * 2,
                     B + (long)(c * 32 + r) * ldb + n0 + ch * 8);
            }
        }
    };

    load_stage(0); cp_commit();
    load_stage(1); cp_commit();
    load_stage(2); cp_commit();

    float acc[4][4][4] = {};
    for (int c = 0; c < nk; c++) {
        cp_wait<2>();
        __syncthreads();
        if (c + 3 < nk) load_stage(c + 3);
        cp_commit();

        const uint32_t so = (uint32_t)((c & 3) * STG) * 2;
        #pragma unroll
        for (int kk = 0; kk < 2; kk++) {
            const int ks = kk * 16;
            uint32_t af[4][4], bf[4][2];
            #pragma unroll
            for (int mi = 0; mi < 4; mi++)
                ldm_x4(af[mi], aAddr[mi] + so + ks * 2);
            #pragma unroll
            for (int p = 0; p < 2; p++) {
                uint32_t r4[4];
                if (BKM) ldm_x4(r4, bAddr[p] + so + ks * 2);
                else     ldm_x4_t(r4, bAddr[p] + so + ks * (BST * 2));
                bf[2 * p + 0][0] = r4[0]; bf[2 * p + 0][1] = r4[1];
                bf[2 * p + 1][0] = r4[2]; bf[2 * p + 1][1] = r4[3];
            }
            #pragma unroll
            for (int mi = 0; mi < 4; mi++)
                #pragma unroll
                for (int ni = 0; ni < 4; ni++)
                    mma16816(acc[mi][ni], af[mi], bf[ni]);
        }
    }

    // ---- epilogue
    const int g = lane >> 2, t2 = (lane & 3) << 1;
    #pragma unroll
    for (int mi = 0; mi < 4; mi++) {
        #pragma unroll
        for (int half = 0; half < 2; half++) {
            long r = m0 + wm * 64 + mi * 16 + g + half * 8;
            #pragma unroll
            for (int ni = 0; ni < 4; ni++) {
                int c = n0 + wn * 32 + ni * 8 + t2;
                float v0 = acc[mi][ni][half * 2 + 0];
                float v1 = acc[mi][ni][half * 2 + 1];
                if (MODE == 1) {
                    v0 = siluf(v0 + bias[c]); v1 = siluf(v1 + bias[c + 1]);
                    *(float2*)(C + r * (long)ldc + c) = make_float2(v0, v1);
                    *(__half2*)(CH + r * (long)ldch + c) = __floats2half2_rn(v0, v1);
                } else if (MODE == 2) {
                    const float2 gt = *(const float2*)(aux + r * (long)ldaux + c);
                    v0 *= gt.x; v1 *= gt.y;
                    *(__half2*)(CH + r * (long)ldch + c) = __floats2half2_rn(v0, v1);
                } else if (MODE == 3) {
                    const float2 sres = *(const float2*)(aux + r * (long)ldaux + c);
                    v0 = (v0 + bias[c]) * (1.f + alpha[c]) + sres.x;
                    v1 = (v1 + bias[c + 1]) * (1.f + alpha[c + 1]) + sres.y;
                    *(float2*)(C + r * (long)ldc + c) = make_float2(v0, v1);
                } else {
                    int d0 = (int)r - c;     d0 = d0 < -64 ? -64 : (d0 > 64 ? 64 : d0);
                    int d1 = (int)r - c - 1; d1 = d1 < -64 ? -64 : (d1 > 64 ? 64 : d1);
                    v0 += bias[c] + rel[d0 + 64];
                    v1 += bias[c + 1] + rel[d1 + 64];
                    *(float2*)(C + r * (long)ldc + c) = make_float2(v0, v1);
                }
            }
        }
    }
}

// ---------------- q/k build + RoPE -> fp16 ----------------------------------
__global__ void qk_rope_k(const float* __restrict__ h, const float* __restrict__ mw,
                          const float* __restrict__ mb, const float* __restrict__ scal,
                          __half* __restrict__ q, __half* __restrict__ k) {
    const int row = blockIdx.x;
    const int t   = threadIdx.x;           // 0..127
    const int pos = row & (LL - 1);
    const float* base = h + (long)row * GVA_N + 2 * PROJ;
    float b0 = base[t], b1 = base[t + 128];
    float q0 = fmaf(b0, mw[t],       mb[t]);
    float q1 = fmaf(b1, mw[t + 128], mb[t + 128]);
    float k0 = fmaf(b0, mw[256 + t],       mb[256 + t]);
    float k1 = fmaf(b1, mw[256 + t + 128], mb[256 + t + 128]);
    float freq = exp2f(-(float)t * (13.287712379549449f / 128.f));
    float ang = (float)pos * freq;
    float sn, cs; sincosf(ang, &sn, &cs);
    float sc = scal[row];
    q[(long)row * 256 + t]       = __float2half_rn((q0 * cs - q1 * sn) * sc);
    q[(long)row * 256 + t + 128] = __float2half_rn((q1 * cs + q0 * sn) * sc);
    k[(long)row * 256 + t]       = __float2half_rn(k0 * cs - k1 * sn);
    k[(long)row * 256 + t + 128] = __float2half_rn(k1 * cs + k0 * sn);
}

// ---------------- row softmax over 1024: fp32 + fp16 outputs -----------------
__global__ __launch_bounds__(256) void softmax_k(float* __restrict__ S,
                                                 __half* __restrict__ S16) {
    float4* p = (float4*)(S + (long)blockIdx.x * LL);
    __half2* p16 = (__half2*)(S16 + (long)blockIdx.x * LL);
    float4 v = p[threadIdx.x];
    __shared__ float rm[8], rs[8];
    float m = fmaxf(fmaxf(v.x, v.y), fmaxf(v.z, v.w));
    m = warpMax(m);
    if ((threadIdx.x & 31) == 0) rm[threadIdx.x >> 5] = m;
    __syncthreads();
    m = rm[0];
    #pragma unroll
    for (int i = 1; i < 8; i++) m = fmaxf(m, rm[i]);
    v.x = __expf(v.x - m); v.y = __expf(v.y - m);
    v.z = __expf(v.z - m); v.w = __expf(v.w - m);
    float s = v.x + v.y + v.z + v.w;
    s = warpSum(s);
    if ((threadIdx.x & 31) == 0) rs[threadIdx.x >> 5] = s;
    __syncthreads();
    s = 0.f;
    #pragma unroll
    for (int i = 0; i < 8; i++) s += rs[i];
    float inv = 1.f / s;
    v.x *= inv; v.y *= inv; v.z *= inv; v.w *= inv;
    p[threadIdx.x] = v;
    p16[threadIdx.x * 2 + 0] = __floats2half2_rn(v.x, v.y);
    p16[threadIdx.x * 2 + 1] = __floats2half2_rn(v.z, v.w);
}

// ---------------- edge = attn[0] + attn[1] (fp32) ----------------------------
__global__ void edge_k(const float* __restrict__ attn, float* __restrict__ e) {
    long i = (long)blockIdx.x * 256 + threadIdx.x;
    float4 a = ((const float4*)attn)[i];
    float4 b = ((const float4*)(attn + (long)LL * LL))[i];
    ((float4*)e)[i] = make_float4(a.x + b.x, a.y + b.y, a.z + b.z, a.w + b.w);
}

// ---------------- launch ------------------------------------------------------
extern "C" void kernel_launch(void* const* d_in, const int* in_sizes, int n_in,
                              void* d_out, int out_size) {
    const float* node      = (const float*)d_in[0];
    const float* qk_scal   = (const float*)d_in[1];
    const float* bias      = (const float*)d_in[2];
    const float* cond      = (const float*)d_in[3];
    const float* w_gva     = (const float*)d_in[4];
    const float* b_gva     = (const float*)d_in[5];
    const float* mhs_w     = (const float*)d_in[6];
    const float* mhs_b     = (const float*)d_in[7];
    const float* relpos    = (const float*)d_in[8];
    const float* w_out     = (const float*)d_in[9];
    const float* b_out     = (const float*)d_in[10];
    const float* w_adaln   = (const float*)d_in[11];
    const float* b_adaln   = (const float*)d_in[12];
    float* out = (float*)d_out;

    float *sc, *part, *gba, *h, *attn, *nodeb;
    __half *x16, *h16, *q16, *k16, *attn16, *av16, *wg16, *wo16;
    cudaGetSymbolAddress((void**)&sc,     d_sc);
    cudaGetSymbolAddress((void**)&part,   d_part);
    cudaGetSymbolAddress((void**)&gba,    d_gba);
    cudaGetSymbolAddress((void**)&x16,    d_x16);
    cudaGetSymbolAddress((void**)&h,      d_h);
    cudaGetSymbolAddress((void**)&h16,    d_h16);
    cudaGetSymbolAddress((void**)&q16,    d_q16);
    cudaGetSymbolAddress((void**)&k16,    d_k16);
    cudaGetSymbolAddress((void**)&attn,   d_attn);
    cudaGetSymbolAddress((void**)&attn16, d_attn16);
    cudaGetSymbolAddress((void**)&av16,   d_av16);
    cudaGetSymbolAddress((void**)&nodeb,  d_node);
    cudaGetSymbolAddress((void**)&wg16,   d_wgva16);
    cudaGetSymbolAddress((void**)&wo16,   d_wout16);

    const int SMW = 4 * (ASZ + 32 * 136) * 2;    // 75776 (weights B)
    const int SMK = 4 * (ASZ + 128 * 40) * 2;    // 81920 (k-major B)
    cudaFuncSetAttribute(hgemm<1, false>, cudaFuncAttributeMaxDynamicSharedMemorySize, SMW);
    cudaFuncSetAttribute(hgemm<2, false>, cudaFuncAttributeMaxDynamicSharedMemorySize, SMW);
    cudaFuncSetAttribute(hgemm<3, false>, cudaFuncAttributeMaxDynamicSharedMemorySize, SMW);
    cudaFuncSetAttribute(hgemm<4, true>,  cudaFuncAttributeMaxDynamicSharedMemorySize, SMK);

    cudaMemcpyAsync(nodeb, node, (size_t)ROWS * NODE * sizeof(float),
                    cudaMemcpyDeviceToDevice);
    // one-time weight conversions
    f2h_k<<<(int)((long)NL * NODE * GVA_N / 1024), 256>>>(w_gva, wg16);
    f2h_k<<<(int)((long)NL * PROJ * NODE / 1024), 256>>>(w_out, wo16);

    silu_vec_k<<<(BB * NODE + 255) / 256, 256>>>(cond, sc, BB * NODE);
    adaln_part_k<<<dim3(ADALN_N / 256, BB * KSLICE, NL), 256>>>(sc, w_adaln, part);
    adaln_reduce_k<<<(NL * BB * ADALN_N) / 256, 256>>>(part, b_adaln, gba);

    for (int l = 0; l < NL; l++) {
        const float* gba_l = gba + (long)l * BB * ADALN_N;

        ln_mod_k<<<ROWS, 256>>>(nodeb, gba_l, x16);

        // h = silu(x @ w_gva + b_gva)   [2048 x 5376 x 1280]
        hgemm<1, false><<<dim3(GVA_N / 128, ROWS / 128, 1), 256, SMW>>>(
            NODE,
            x16, NODE, 0L,
            wg16 + (long)l * NODE * GVA_N, GVA_N, 0L,
            h, GVA_N, 0L,
            h16, GVA_N, 0L,
            b_gva + l * GVA_N,
            nullptr, 0, 0L, nullptr, 0, nullptr);

        qk_rope_k<<<ROWS, 128>>>(h, mhs_w + l * 2 * ATTND, mhs_b + l * 2 * ATTND,
                                 qk_scal, q16, k16);

        // logits = q @ k^T + bias + rel   [1024 x 1024 x 256] x2
        hgemm<4, true><<<dim3(LL / 128, LL / 128, BB), 256, SMK>>>(
            ATTND,
            q16, ATTND, (long)LL * ATTND,
            k16, ATTND, (long)LL * ATTND,
            attn, LL, (long)LL * LL,
            nullptr, 0, 0L,
            bias,
            nullptr, 0, 0L, nullptr, 0,
            relpos + l * NREL);

        softmax_k<<<ROWS, 256>>>(attn, attn16);

        if (l == NL - 1)
            edge_k<<<(LL * LL / 4) / 256, 256>>>(attn, out + (long)ROWS * NODE);

        // av = (attn @ values) * gates   [1024 x 2560 x 1024] x2
        hgemm<2, false><<<dim3(PROJ / 128, LL / 128, BB), 256, SMW>>>(
            LL,
            attn16, LL, (long)LL * LL,
            h16 + PROJ, GVA_N, (long)LL * GVA_N,
            nullptr, 0, 0L,
            av16, PROJ, (long)LL * PROJ,
            nullptr,
            h, GVA_N, (long)LL * GVA_N,      // gates (fp32)
            nullptr, 0, nullptr);

        // node = (av @ w_out + b_out)*(1+alpha) + shortcut  [1024 x 1280 x 2560] x2
        float* Cdst = (l == NL - 1) ? out : nodeb;
        hgemm<3, false><<<dim3(NODE / 128, LL / 128, BB), 256, SMW>>>(
            PROJ,
            av16, PROJ, (long)LL * PROJ,
            wo16 + (long)l * PROJ * NODE, NODE, 0L,
            Cdst, NODE, (long)LL * NODE,
            nullptr, 0, 0L,
            b_out + l * NODE,
            nodeb, NODE, (long)LL * NODE,    // residual (fp32)
            gba_l + 2 * NODE, ADALN_N, nullptr);
    }
    (void)in_sizes; (void)n_in; (void)out_size;
}

// round 7
// speedup vs baseline: 7.4068x; 1.0312x over previous
#include <cuda_runtime.h>
#include <cuda_fp16.h>
#include <cstdint>
#include <math.h>

#define NODE   1280
#define PROJ   2560
#define ATTND  256
#define NREL   129
#define NL     4
#define BB     2
#define LL     1024
#define GVA_N  (2*PROJ + ATTND)   // 5376
#define ADALN_N (3*NODE)          // 3840
#define ROWS   (BB*LL)            // 2048
#define KSLICE 4

// ---------------- scratch (device globals; no allocation allowed) ----------
__device__ float  d_sc    [BB*NODE];
__device__ float  d_part  [NL*BB*KSLICE*ADALN_N];
__device__ float  d_gba   [NL*BB*ADALN_N];
__device__ __half d_x16   [ROWS*NODE];
__device__ __half d_h16   [ROWS*GVA_N];
__device__ __half d_q16   [ROWS*ATTND];
__device__ __half d_k16   [ROWS*ATTND];
__device__ float  d_attn  [(long)BB*LL*LL];
__device__ __half d_attn16[(long)BB*LL*LL];
__device__ __half d_av16  [ROWS*PROJ];
__device__ float  d_node  [ROWS*NODE];
__device__ __half d_wgva16[(long)NL*NODE*GVA_N];
__device__ __half d_wout16[(long)NL*PROJ*NODE];

// ---------------- helpers ---------------------------------------------------
__device__ __forceinline__ float siluf(float x) { return x / (1.f + __expf(-x)); }
__device__ __forceinline__ float warpMax(float v) {
    #pragma unroll
    for (int o = 16; o > 0; o >>= 1) v = fmaxf(v, __shfl_xor_sync(0xffffffffu, v, o));
    return v;
}
__device__ __forceinline__ float warpSum(float v) {
    #pragma unroll
    for (int o = 16; o > 0; o >>= 1) v += __shfl_xor_sync(0xffffffffu, v, o);
    return v;
}
__device__ __forceinline__ uint32_t smem_u32(const void* p) {
    uint32_t a;
    asm("{ .reg .u64 t; cvta.to.shared.u64 t, %1; cvt.u32.u64 %0, t; }"
        : "=r"(a) : "l"(p));
    return a;
}
__device__ __forceinline__ void cp16(uint32_t dst, const void* src) {
    asm volatile("cp.async.cg.shared.global [%0], [%1], 16;" :: "r"(dst), "l"(src));
}
__device__ __forceinline__ void cp_commit() {
    asm volatile("cp.async.commit_group;" ::: "memory");
}
template <int N>
__device__ __forceinline__ void cp_wait() {
    asm volatile("cp.async.wait_group %0;" :: "n"(N) : "memory");
}
__device__ __forceinline__ void ldm_x4(uint32_t* r, uint32_t a) {
    asm volatile("ldmatrix.sync.aligned.m8n8.x4.shared.b16 {%0,%1,%2,%3}, [%4];"
                 : "=r"(r[0]), "=r"(r[1]), "=r"(r[2]), "=r"(r[3]) : "r"(a));
}
__device__ __forceinline__ void ldm_x4_t(uint32_t* r, uint32_t a) {
    asm volatile("ldmatrix.sync.aligned.m8n8.x4.trans.shared.b16 {%0,%1,%2,%3}, [%4];"
                 : "=r"(r[0]), "=r"(r[1]), "=r"(r[2]), "=r"(r[3]) : "r"(a));
}
__device__ __forceinline__ void mma16816(float* c, const uint32_t* a, const uint32_t* b) {
    asm volatile(
        "mma.sync.aligned.m16n8k16.row.col.f32.f16.f16.f32 "
        "{%0,%1,%2,%3}, {%4,%5,%6,%7}, {%8,%9}, {%0,%1,%2,%3};"
        : "+f"(c[0]), "+f"(c[1]), "+f"(c[2]), "+f"(c[3])
        : "r"(a[0]), "r"(a[1]), "r"(a[2]), "r"(a[3]), "r"(b[0]), "r"(b[1]));
}

// ---------------- small kernels ---------------------------------------------
__global__ void silu_vec_k(const float* __restrict__ c, float* __restrict__ sc, int n) {
    int i = blockIdx.x * 256 + threadIdx.x;
    if (i < n) sc[i] = siluf(c[i]);
}

__global__ void f2h_k(const float* __restrict__ in, __half* __restrict__ out) {
    long i = (long)blockIdx.x * 256 + threadIdx.x;
    float4 v = ((const float4*)in)[i];
    ((__half2*)out)[2 * i]     = __floats2half2_rn(v.x, v.y);
    ((__half2*)out)[2 * i + 1] = __floats2half2_rn(v.z, v.w);
}

__global__ void adaln_part_k(const float* __restrict__ sc, const float* __restrict__ w,
                             float* __restrict__ part) {
    const int l = blockIdx.z, b = blockIdx.y >> 2, ks = blockIdx.y & 3;
    const int col = blockIdx.x * 256 + threadIdx.x;
    const int KC = NODE / KSLICE;              // 320
    const float* s  = sc + b * NODE + ks * KC;
    const float* wp = w + (long)l * NODE * ADALN_N + (long)ks * KC * ADALN_N + col;
    float a0 = 0.f, a1 = 0.f;
    #pragma unroll 8
    for (int k = 0; k < KC; k += 2) {
        a0 = fmaf(s[k],     wp[(long)k * ADALN_N],       a0);
        a1 = fmaf(s[k + 1], wp[(long)(k + 1) * ADALN_N], a1);
    }
    part[((((long)l * BB) + b) * KSLICE + ks) * ADALN_N + col] = a0 + a1;
}
__global__ void adaln_reduce_k(const float* __restrict__ part,
                               const float* __restrict__ bvec, float* __restrict__ gba) {
    long idx = (long)blockIdx.x * 256 + threadIdx.x;
    int l = (int)(idx / (BB * ADALN_N));
    int rem = (int)(idx % (BB * ADALN_N));
    int b = rem / ADALN_N, col = rem % ADALN_N;
    const float* p = part + (((long)l * BB + b) * KSLICE) * ADALN_N + col;
    gba[idx] = bvec[l * ADALN_N + col] + p[0] + p[ADALN_N] + p[2 * ADALN_N] + p[3 * ADALN_N];
}

// LayerNorm + modulate -> fp16 x
__global__ __launch_bounds__(256) void ln_mod_k(const float* __restrict__ node,
                                                const float* __restrict__ gba,
                                                __half* __restrict__ x16) {
    const int row = blockIdx.x;
    const int b   = row >> 10;
    const float* p = node + (long)row * NODE;
    float vals[5];
    float s = 0.f, sq = 0.f;
    #pragma unroll
    for (int i = 0; i < 5; i++) {
        float v = p[threadIdx.x + i * 256];
        vals[i] = v; s += v; sq += v * v;
    }
    __shared__ float rs[8], rq[8];
    s = warpSum(s); sq = warpSum(sq);
    if ((threadIdx.x & 31) == 0) { rs[threadIdx.x >> 5] = s; rq[threadIdx.x >> 5] = sq; }
    __syncthreads();
    float ts = 0.f, tq = 0.f;
    #pragma unroll
    for (int i = 0; i < 8; i++) { ts += rs[i]; tq += rq[i]; }
    const float mean = ts * (1.f / NODE);
    const float var  = tq * (1.f / NODE) - mean * mean;
    const float rstd = rsqrtf(var + 1e-5f);
    const float* g = gba + (long)b * ADALN_N;
    __half* xo = x16 + (long)row * NODE;
    #pragma unroll
    for (int i = 0; i < 5; i++) {
        int c = threadIdx.x + i * 256;
        float v = (vals[i] - mean) * rstd;
        xo[c] = __float2half_rn(v * (1.f + g[c]) + g[NODE + c]);
    }
}

// ============================================================================
// fp16 mma.sync GEMM: CTA tile 128x128, 4 warps (64x64 warp tile), BK=32,
// 4-stage cp.async pipeline, ldmatrix fragments, fp32 accum.
// A: fp16 [M,K] row-major.
// B: BKM=false -> fp16 [K,N] row-major; SMEM [k][n], ldmatrix.trans
//    BKM=true  -> fp16 [N,K] row-major; SMEM [n][k], ldmatrix
// MODE 1: CH = silu(acc + bias[n])                 (fp16 out only)
// MODE 2: CH = acc * auxH[m,n]                     (fp16 gates, fp16 out)
// MODE 3: C  = (acc + bias[n])*(1+alpha[n]) + auxF (fp32 out)
// MODE 4: C  = acc + bias[z,n] + rel[clamp(m-n)]   (fp32 out)
// ============================================================================
#define AST 40              // A row stride (halfs)
#define ASZ (128*AST)       // 5120 halfs

template <int MODE, bool BKM>
__global__ __launch_bounds__(128, 2) void hgemm(
    int K,
    const __half* __restrict__ A, int lda, long sA,
    const __half* __restrict__ B, int ldb, long sB,
    float* __restrict__ C, int ldc, long sC,
    __half* __restrict__ CH, int ldch, long sCh,
    const float* __restrict__ bias,
    const __half* __restrict__ auxH, int ldaux, long sAux,
    const float* __restrict__ auxF,
    const float* __restrict__ alphaP, int sAlpha,
    const float* __restrict__ rel) {
    constexpr int BST = BKM ? 40 : 136;
    constexpr int BSZ = BKM ? 128 * 40 : 32 * 136;
    constexpr int STG = ASZ + BSZ;                 // halfs per stage

    extern __shared__ __half sh[];
    const int z = blockIdx.z;
    A += z * sA; B += z * sB;
    if (MODE == 3 || MODE == 4) C += z * sC;
    if (MODE == 1 || MODE == 2) CH += z * sCh;
    if (MODE == 2) auxH += z * sAux;
    if (MODE == 3) auxF += z * sAux;
    if (MODE == 4) bias += (long)z * LL;
    const float* alpha = (MODE == 3) ? (alphaP + (long)z * sAlpha) : nullptr;

    const int tid = threadIdx.x, wid = tid >> 5, lane = tid & 31;
    const int wm = wid & 1, wn = wid >> 1;
    const int m0 = blockIdx.y * 128, n0 = blockIdx.x * 128;
    const uint32_t smb = smem_u32(sh);
    const int nk = K >> 5;

    // ---- ldmatrix base addresses (stage 0, k=0), bytes
    uint32_t aAddr[4], bAddr[4];
    #pragma unroll
    for (int mi = 0; mi < 4; mi++) {
        int off = (wm * 64 + mi * 16 + (lane & 15)) * AST + ((lane >> 4) << 3);
        aAddr[mi] = smb + off * 2;
    }
    #pragma unroll
    for (int p = 0; p < 4; p++) {
        int off;
        if (BKM) // SMEM [n][k]
            off = (wn * 64 + p * 16 + (lane & 7) + ((lane >> 4) << 3)) * BST
                  + (((lane >> 3) & 1) << 3);
        else     // SMEM [k][n]
            off = (lane & 15) * BST + wn * 64 + p * 16 + ((lane >> 4) << 3);
        bAddr[p] = smb + (ASZ + off) * 2;
    }

    // ---- stage loader (128 threads)
    auto load_stage = [&](int c) {
        const int slot = c & 3;
        const uint32_t ab = smb + (uint32_t)(slot * STG) * 2;
        const uint32_t bb = ab + ASZ * 2;
        #pragma unroll
        for (int i = 0; i < 4; i++) {           // A: 128 x 32 halfs
            int v = tid + i * 128;
            int r = v >> 2, ch = v & 3;
            cp16(ab + (uint32_t)(r * AST + ch * 8) * 2,
                 A + (long)(m0 + r) * lda + c * 32 + ch * 8);
        }
        if (BKM) {
            #pragma unroll
            for (int i = 0; i < 4; i++) {       // B: 128 n-rows x 32 halfs
                int v = tid + i * 128;
                int r = v >> 2, ch = v & 3;
                cp16(bb + (uint32_t)(r * BST + ch * 8) * 2,
                     B + (long)(n0 + r) * ldb + c * 32 + ch * 8);
            }
        } else {
            #pragma unroll
            for (int i = 0; i < 4; i++) {       // B: 32 k-rows x 128 halfs
                int v = tid + i * 128;
                int r = v >> 4, ch = v & 15;
                cp16(bb + (uint32_t)(r * BST + ch * 8) * 2,
                     B + (long)(c * 32 + r) * ldb + n0 + ch * 8);
            }
        }
    };

    load_stage(0); cp_commit();
    load_stage(1); cp_commit();
    load_stage(2); cp_commit();

    float acc[4][8][4] = {};
    for (int c = 0; c < nk; c++) {
        cp_wait<2>();
        __syncthreads();
        if (c + 3 < nk) load_stage(c + 3);
        cp_commit();

        const uint32_t so = (uint32_t)((c & 3) * STG) * 2;
        #pragma unroll
        for (int kk = 0; kk < 2; kk++) {
            const int ks = kk * 16;
            uint32_t af[4][4], bf[8][2];
            #pragma unroll
            for (int mi = 0; mi < 4; mi++)
                ldm_x4(af[mi], aAddr[mi] + so + ks * 2);
            #pragma unroll
            for (int p = 0; p < 4; p++) {
                uint32_t r4[4];
                if (BKM) ldm_x4(r4, bAddr[p] + so + ks * 2);
                else     ldm_x4_t(r4, bAddr[p] + so + ks * (BST * 2));
                bf[2 * p + 0][0] = r4[0]; bf[2 * p + 0][1] = r4[1];
                bf[2 * p + 1][0] = r4[2]; bf[2 * p + 1][1] = r4[3];
            }
            #pragma unroll
            for (int mi = 0; mi < 4; mi++)
                #pragma unroll
                for (int ni = 0; ni < 8; ni++)
                    mma16816(acc[mi][ni], af[mi], bf[ni]);
        }
    }

    // ---- epilogue
    const int g = lane >> 2, t2 = (lane & 3) << 1;
    #pragma unroll
    for (int mi = 0; mi < 4; mi++) {
        #pragma unroll
        for (int half = 0; half < 2; half++) {
            long r = m0 + wm * 64 + mi * 16 + g + half * 8;
            #pragma unroll
            for (int ni = 0; ni < 8; ni++) {
                int c = n0 + wn * 64 + ni * 8 + t2;
                float v0 = acc[mi][ni][half * 2 + 0];
                float v1 = acc[mi][ni][half * 2 + 1];
                if (MODE == 1) {
                    v0 = siluf(v0 + bias[c]); v1 = siluf(v1 + bias[c + 1]);
                    *(__half2*)(CH + r * (long)ldch + c) = __floats2half2_rn(v0, v1);
                } else if (MODE == 2) {
                    const __half2 gt = *(const __half2*)(auxH + r * (long)ldaux + c);
                    v0 *= __half2float(gt.x); v1 *= __half2float(gt.y);
                    *(__half2*)(CH + r * (long)ldch + c) = __floats2half2_rn(v0, v1);
                } else if (MODE == 3) {
                    const float2 sres = *(const float2*)(auxF + r * (long)ldaux + c);
                    v0 = (v0 + bias[c]) * (1.f + alpha[c]) + sres.x;
                    v1 = (v1 + bias[c + 1]) * (1.f + alpha[c + 1]) + sres.y;
                    *(float2*)(C + r * (long)ldc + c) = make_float2(v0, v1);
                } else {
                    int d0 = (int)r - c;     d0 = d0 < -64 ? -64 : (d0 > 64 ? 64 : d0);
                    int d1 = (int)r - c - 1; d1 = d1 < -64 ? -64 : (d1 > 64 ? 64 : d1);
                    v0 += bias[c] + rel[d0 + 64];
                    v1 += bias[c + 1] + rel[d1 + 64];
                    *(float2*)(C + r * (long)ldc + c) = make_float2(v0, v1);
                }
            }
        }
    }
}

// ---------------- q/k build + RoPE (reads fp16 h) ----------------------------
__global__ void qk_rope_k(const __half* __restrict__ h, const float* __restrict__ mw,
                          const float* __restrict__ mb, const float* __restrict__ scal,
                          __half* __restrict__ q, __half* __restrict__ k) {
    const int row = blockIdx.x;
    const int t   = threadIdx.x;           // 0..127
    const int pos = row & (LL - 1);
    const __half* base = h + (long)row * GVA_N + 2 * PROJ;
    float b0 = __half2float(base[t]), b1 = __half2float(base[t + 128]);
    float q0 = fmaf(b0, mw[t],       mb[t]);
    float q1 = fmaf(b1, mw[t + 128], mb[t + 128]);
    float k0 = fmaf(b0, mw[256 + t],       mb[256 + t]);
    float k1 = fmaf(b1, mw[256 + t + 128], mb[256 + t + 128]);
    float freq = exp2f(-(float)t * (13.287712379549449f / 128.f));
    float ang = (float)pos * freq;
    float sn, cs; sincosf(ang, &sn, &cs);
    float sc = scal[row];
    q[(long)row * 256 + t]       = __float2half_rn((q0 * cs - q1 * sn) * sc);
    q[(long)row * 256 + t + 128] = __float2half_rn((q1 * cs + q0 * sn) * sc);
    k[(long)row * 256 + t]       = __float2half_rn(k0 * cs - k1 * sn);
    k[(long)row * 256 + t + 128] = __float2half_rn(k1 * cs + k0 * sn);
}

// ---------------- row softmax over 1024: fp32 + fp16 outputs -----------------
__global__ __launch_bounds__(256) void softmax_k(float* __restrict__ S,
                                                 __half* __restrict__ S16) {
    float4* p = (float4*)(S + (long)blockIdx.x * LL);
    __half2* p16 = (__half2*)(S16 + (long)blockIdx.x * LL);
    float4 v = p[threadIdx.x];
    __shared__ float rm[8], rs[8];
    float m = fmaxf(fmaxf(v.x, v.y), fmaxf(v.z, v.w));
    m = warpMax(m);
    if ((threadIdx.x & 31) == 0) rm[threadIdx.x >> 5] = m;
    __syncthreads();
    m = rm[0];
    #pragma unroll
    for (int i = 1; i < 8; i++) m = fmaxf(m, rm[i]);
    v.x = __expf(v.x - m); v.y = __expf(v.y - m);
    v.z = __expf(v.z - m); v.w = __expf(v.w - m);
    float s = v.x + v.y + v.z + v.w;
    s = warpSum(s);
    if ((threadIdx.x & 31) == 0) rs[threadIdx.x >> 5] = s;
    __syncthreads();
    s = 0.f;
    #pragma unroll
    for (int i = 0; i < 8; i++) s += rs[i];
    float inv = 1.f / s;
    v.x *= inv; v.y *= inv; v.z *= inv; v.w *= inv;
    p[threadIdx.x] = v;
    p16[threadIdx.x * 2 + 0] = __floats2half2_rn(v.x, v.y);
    p16[threadIdx.x * 2 + 1] = __floats2half2_rn(v.z, v.w);
}

// ---------------- edge = attn[0] + attn[1] (fp32) ----------------------------
__global__ void edge_k(const float* __restrict__ attn, float* __restrict__ e) {
    long i = (long)blockIdx.x * 256 + threadIdx.x;
    float4 a = ((const float4*)attn)[i];
    float4 b = ((const float4*)(attn + (long)LL * LL))[i];
    ((float4*)e)[i] = make_float4(a.x + b.x, a.y + b.y, a.z + b.z, a.w + b.w);
}

// ---------------- launch ------------------------------------------------------
extern "C" void kernel_launch(void* const* d_in, const int* in_sizes, int n_in,
                              void* d_out, int out_size) {
    const float* node      = (const float*)d_in[0];
    const float* qk_scal   = (const float*)d_in[1];
    const float* bias      = (const float*)d_in[2];
    const float* cond      = (const float*)d_in[3];
    const float* w_gva     = (const float*)d_in[4];
    const float* b_gva     = (const float*)d_in[5];
    const float* mhs_w     = (const float*)d_in[6];
    const float* mhs_b     = (const float*)d_in[7];
    const float* relpos    = (const float*)d_in[8];
    const float* w_out     = (const float*)d_in[9];
    const float* b_out     = (const float*)d_in[10];
    const float* w_adaln   = (const float*)d_in[11];
    const float* b_adaln   = (const float*)d_in[12];
    float* out = (float*)d_out;

    float *sc, *part, *gba, *attn, *nodeb;
    __half *x16, *h16, *q16, *k16, *attn16, *av16, *wg16, *wo16;
    cudaGetSymbolAddress((void**)&sc,     d_sc);
    cudaGetSymbolAddress((void**)&part,   d_part);
    cudaGetSymbolAddress((void**)&gba,    d_gba);
    cudaGetSymbolAddress((void**)&x16,    d_x16);
    cudaGetSymbolAddress((void**)&h16,    d_h16);
    cudaGetSymbolAddress((void**)&q16,    d_q16);
    cudaGetSymbolAddress((void**)&k16,    d_k16);
    cudaGetSymbolAddress((void**)&attn,   d_attn);
    cudaGetSymbolAddress((void**)&attn16, d_attn16);
    cudaGetSymbolAddress((void**)&av16,   d_av16);
    cudaGetSymbolAddress((void**)&nodeb,  d_node);
    cudaGetSymbolAddress((void**)&wg16,   d_wgva16);
    cudaGetSymbolAddress((void**)&wo16,   d_wout16);

    const int SMW = 4 * (ASZ + 32 * 136) * 2;    // 75776 (weights B)
    const int SMK = 4 * (ASZ + 128 * 40) * 2;    // 81920 (k-major B)
    cudaFuncSetAttribute(hgemm<1, false>, cudaFuncAttributeMaxDynamicSharedMemorySize, SMW);
    cudaFuncSetAttribute(hgemm<2, false>, cudaFuncAttributeMaxDynamicSharedMemorySize, SMW);
    cudaFuncSetAttribute(hgemm<3, false>, cudaFuncAttributeMaxDynamicSharedMemorySize, SMW);
    cudaFuncSetAttribute(hgemm<4, true>,  cudaFuncAttributeMaxDynamicSharedMemorySize, SMK);

    cudaMemcpyAsync(nodeb, node, (size_t)ROWS * NODE * sizeof(float),
                    cudaMemcpyDeviceToDevice);
    f2h_k<<<(int)((long)NL * NODE * GVA_N / 1024), 256>>>(w_gva, wg16);
    f2h_k<<<(int)((long)NL * PROJ * NODE / 1024), 256>>>(w_out, wo16);

    silu_vec_k<<<(BB * NODE + 255) / 256, 256>>>(cond, sc, BB * NODE);
    adaln_part_k<<<dim3(ADALN_N / 256, BB * KSLICE, NL), 256>>>(sc, w_adaln, part);
    adaln_reduce_k<<<(NL * BB * ADALN_N) / 256, 256>>>(part, b_adaln, gba);

    for (int l = 0; l < NL; l++) {
        const float* gba_l = gba + (long)l * BB * ADALN_N;

        ln_mod_k<<<ROWS, 256>>>(nodeb, gba_l, x16);

        // h16 = silu(x @ w_gva + b_gva)   [2048 x 5376 x 1280]
        hgemm<1, false><<<dim3(GVA_N / 128, ROWS / 128, 1), 128, SMW>>>(
            NODE,
            x16, NODE, 0L,
            wg16 + (long)l * NODE * GVA_N, GVA_N, 0L,
            nullptr, 0, 0L,
            h16, GVA_N, 0L,
            b_gva + l * GVA_N,
            nullptr, 0, 0L, nullptr, nullptr, 0, nullptr);

        qk_rope_k<<<ROWS, 128>>>(h16, mhs_w + l * 2 * ATTND, mhs_b + l * 2 * ATTND,
                                 qk_scal, q16, k16);

        // logits = q @ k^T + bias + rel   [1024 x 1024 x 256] x2
        hgemm<4, true><<<dim3(LL / 128, LL / 128, BB), 128, SMK>>>(
            ATTND,
            q16, ATTND, (long)LL * ATTND,
            k16, ATTND, (long)LL * ATTND,
            attn, LL, (long)LL * LL,
            nullptr, 0, 0L,
            bias,
            nullptr, 0, 0L, nullptr, nullptr, 0,
            relpos + l * NREL);

        softmax_k<<<ROWS, 256>>>(attn, attn16);

        if (l == NL - 1)
            edge_k<<<(LL * LL / 4) / 256, 256>>>(attn, out + (long)ROWS * NODE);

        // av16 = (attn @ values) * gates   [1024 x 2560 x 1024] x2
        hgemm<2, false><<<dim3(PROJ / 128, LL / 128, BB), 128, SMW>>>(
            LL,
            attn16, LL, (long)LL * LL,
            h16 + PROJ, GVA_N, (long)LL * GVA_N,
            nullptr, 0, 0L,
            av16, PROJ, (long)LL * PROJ,
            nullptr,
            h16, GVA_N, (long)LL * GVA_N,    // gates fp16
            nullptr, nullptr, 0, nullptr);

        // node = (av @ w_out + b_out)*(1+alpha) + shortcut  [1024 x 1280 x 2560] x2
        float* Cdst = (l == NL - 1) ? out : nodeb;
        hgemm<3, false><<<dim3(NODE / 128, LL / 128, BB), 128, SMW>>>(
            PROJ,
            av16, PROJ, (long)LL * PROJ,
            wo16 + (long)l * PROJ * NODE, NODE, 0L,
            Cdst, NODE, (long)LL * NODE,
            nullptr, 0, 0L,
            b_out + l * NODE,
            nullptr, NODE, (long)LL * NODE,
            nodeb,                            // residual fp32
            gba_l + 2 * NODE, ADALN_N, nullptr);
    }
    (void)in_sizes; (void)n_in; (void)out_size;
}

// round 8
// speedup vs baseline: 7.6841x; 1.0374x over previous
#include <cuda_runtime.h>
#include <cuda_fp16.h>
#include <cstdint>
#include <math.h>

#define NODE   1280
#define PROJ   2560
#define ATTND  256
#define NREL   129
#define NL     4
#define BB     2
#define LL     1024
#define GVA_N  (2*PROJ + ATTND)   // 5376
#define ADALN_N (3*NODE)          // 3840
#define ROWS   (BB*LL)            // 2048
#define KS     10                 // adaLN split-K factor

// ---------------- scratch (device globals; no allocation allowed) ----------
__device__ float  d_sc    [BB*NODE];
__device__ float  d_part  [NL*BB*KS*ADALN_N];
__device__ float  d_gba   [NL*BB*ADALN_N];
__device__ __half d_x16   [ROWS*NODE];
__device__ __half d_h16   [ROWS*GVA_N];
__device__ __half d_q16   [ROWS*ATTND];
__device__ __half d_k16   [ROWS*ATTND];
__device__ float  d_attn  [(long)BB*LL*LL];
__device__ __half d_attn16[(long)BB*LL*LL];
__device__ __half d_av16  [ROWS*PROJ];
__device__ float  d_node  [ROWS*NODE];
__device__ __half d_wgva16[(long)NL*NODE*GVA_N];
__device__ __half d_wout16[(long)NL*PROJ*NODE];

// ---------------- helpers ---------------------------------------------------
__device__ __forceinline__ float siluf(float x) { return x / (1.f + __expf(-x)); }
__device__ __forceinline__ float warpMax(float v) {
    #pragma unroll
    for (int o = 16; o > 0; o >>= 1) v = fmaxf(v, __shfl_xor_sync(0xffffffffu, v, o));
    return v;
}
__device__ __forceinline__ float warpSum(float v) {
    #pragma unroll
    for (int o = 16; o > 0; o >>= 1) v += __shfl_xor_sync(0xffffffffu, v, o);
    return v;
}
__device__ __forceinline__ uint32_t smem_u32(const void* p) {
    uint32_t a;
    asm("{ .reg .u64 t; cvta.to.shared.u64 t, %1; cvt.u32.u64 %0, t; }"
        : "=r"(a) : "l"(p));
    return a;
}
__device__ __forceinline__ void cp16(uint32_t dst, const void* src) {
    asm volatile("cp.async.cg.shared.global [%0], [%1], 16;" :: "r"(dst), "l"(src));
}
__device__ __forceinline__ void cp_commit() {
    asm volatile("cp.async.commit_group;" ::: "memory");
}
template <int N>
__device__ __forceinline__ void cp_wait() {
    asm volatile("cp.async.wait_group %0;" :: "n"(N) : "memory");
}
__device__ __forceinline__ void ldm_x4(uint32_t* r, uint32_t a) {
    asm volatile("ldmatrix.sync.aligned.m8n8.x4.shared.b16 {%0,%1,%2,%3}, [%4];"
                 : "=r"(r[0]), "=r"(r[1]), "=r"(r[2]), "=r"(r[3]) : "r"(a));
}
__device__ __forceinline__ void ldm_x4_t(uint32_t* r, uint32_t a) {
    asm volatile("ldmatrix.sync.aligned.m8n8.x4.trans.shared.b16 {%0,%1,%2,%3}, [%4];"
                 : "=r"(r[0]), "=r"(r[1]), "=r"(r[2]), "=r"(r[3]) : "r"(a));
}
__device__ __forceinline__ void mma16816(float* c, const uint32_t* a, const uint32_t* b) {
    asm volatile(
        "mma.sync.aligned.m16n8k16.row.col.f32.f16.f16.f32 "
        "{%0,%1,%2,%3}, {%4,%5,%6,%7}, {%8,%9}, {%0,%1,%2,%3};"
        : "+f"(c[0]), "+f"(c[1]), "+f"(c[2]), "+f"(c[3])
        : "r"(a[0]), "r"(a[1]), "r"(a[2]), "r"(a[3]), "r"(b[0]), "r"(b[1]));
}

// ---------------- small kernels ---------------------------------------------
__global__ void silu_vec_k(const float* __restrict__ c, float* __restrict__ sc, int n) {
    int i = blockIdx.x * 256 + threadIdx.x;
    if (i < n) sc[i] = siluf(c[i]);
}

__global__ void f2h_k(const float* __restrict__ in, __half* __restrict__ out) {
    long i = (long)blockIdx.x * 256 + threadIdx.x;
    float4 v = ((const float4*)in)[i];
    ((__half2*)out)[2 * i]     = __floats2half2_rn(v.x, v.y);
    ((__half2*)out)[2 * i + 1] = __floats2half2_rn(v.z, v.w);
}

__global__ void adaln_part_k(const float* __restrict__ sc, const float* __restrict__ w,
                             float* __restrict__ part) {
    const int l = blockIdx.z;
    const int b = blockIdx.y / KS, ks = blockIdx.y % KS;
    const int col = blockIdx.x * 256 + threadIdx.x;
    const int KC = NODE / KS;                  // 128
    const float* s  = sc + b * NODE + ks * KC;
    const float* wp = w + (long)l * NODE * ADALN_N + (long)ks * KC * ADALN_N + col;
    float a0 = 0.f, a1 = 0.f;
    #pragma unroll 8
    for (int k = 0; k < KC; k += 2) {
        a0 = fmaf(s[k],     wp[(long)k * ADALN_N],       a0);
        a1 = fmaf(s[k + 1], wp[(long)(k + 1) * ADALN_N], a1);
    }
    part[((((long)l * BB) + b) * KS + ks) * ADALN_N + col] = a0 + a1;
}
__global__ void adaln_reduce_k(const float* __restrict__ part,
                               const float* __restrict__ bvec, float* __restrict__ gba) {
    long idx = (long)blockIdx.x * 256 + threadIdx.x;
    int l = (int)(idx / (BB * ADALN_N));
    int rem = (int)(idx % (BB * ADALN_N));
    int b = rem / ADALN_N, col = rem % ADALN_N;
    const float* p = part + (((long)l * BB + b) * KS) * ADALN_N + col;
    float acc = bvec[l * ADALN_N + col];
    #pragma unroll
    for (int i = 0; i < KS; i++) acc += p[(long)i * ADALN_N];
    gba[idx] = acc;
}

// LayerNorm + modulate -> fp16 x
__global__ __launch_bounds__(256) void ln_mod_k(const float* __restrict__ node,
                                                const float* __restrict__ gba,
                                                __half* __restrict__ x16) {
    const int row = blockIdx.x;
    const int b   = row >> 10;
    const float* p = node + (long)row * NODE;
    float vals[5];
    float s = 0.f, sq = 0.f;
    #pragma unroll
    for (int i = 0; i < 5; i++) {
        float v = p[threadIdx.x + i * 256];
        vals[i] = v; s += v; sq += v * v;
    }
    __shared__ float rs[8], rq[8];
    s = warpSum(s); sq = warpSum(sq);
    if ((threadIdx.x & 31) == 0) { rs[threadIdx.x >> 5] = s; rq[threadIdx.x >> 5] = sq; }
    __syncthreads();
    float ts = 0.f, tq = 0.f;
    #pragma unroll
    for (int i = 0; i < 8; i++) { ts += rs[i]; tq += rq[i]; }
    const float mean = ts * (1.f / NODE);
    const float var  = tq * (1.f / NODE) - mean * mean;
    const float rstd = rsqrtf(var + 1e-5f);
    const float* g = gba + (long)b * ADALN_N;
    __half* xo = x16 + (long)row * NODE;
    #pragma unroll
    for (int i = 0; i < 5; i++) {
        int c = threadIdx.x + i * 256;
        float v = (vals[i] - mean) * rstd;
        xo[c] = __float2half_rn(v * (1.f + g[c]) + g[NODE + c]);
    }
}

// ============================================================================
// fp16 mma.sync GEMM: CTA tile MT x 128 (MT=128: 4 warps 64x64; MT=64: 4 warps
// 64x32), BK=32, 4-stage cp.async pipeline, ldmatrix fragments, fp32 accum.
// A: fp16 [M,K] row-major.
// B: BKM=false -> fp16 [K,N] row-major; SMEM [k][n], ldmatrix.trans
//    BKM=true  -> fp16 [N,K] row-major; SMEM [n][k], ldmatrix
// MODE 1: CH = silu(acc + bias[n])                 (fp16 out)
// MODE 2: CH = acc * auxH[m,n]                     (fp16 out)
// MODE 3: C  = (acc + bias[n])*(1+alpha[n]) + auxF (fp32 out)
// MODE 4: C  = acc + bias[z,n] + rel[clamp(m-n)]   (fp32 out)
// ============================================================================
#define AST 40              // A row stride (halfs)

template <int MODE, bool BKM, int MT>
__global__ __launch_bounds__(128, (MT == 64 ? 3 : 2)) void hgemm(
    int K,
    const __half* __restrict__ A, int lda, long sA,
    const __half* __restrict__ B, int ldb, long sB,
    float* __restrict__ C, int ldc, long sC,
    __half* __restrict__ CH, int ldch, long sCh,
    const float* __restrict__ bias,
    const __half* __restrict__ auxH, int ldaux, long sAux,
    const float* __restrict__ auxF,
    const float* __restrict__ alphaP, int sAlpha,
    const float* __restrict__ rel) {
    constexpr int BST = BKM ? 40 : 136;
    constexpr int BSZ = BKM ? 128 * 40 : 32 * 136;
    constexpr int ASZ2 = MT * AST;               // A halfs per stage
    constexpr int STG = ASZ2 + BSZ;              // halfs per stage
    constexpr int NI  = (MT == 128) ? 8 : 4;     // n 8-col frags per warp
    constexpr int BP  = NI / 2;                  // B ldmatrix count

    extern __shared__ __half sh[];
    const int z = blockIdx.z;
    A += z * sA; B += z * sB;
    if (MODE == 3 || MODE == 4) C += z * sC;
    if (MODE == 1 || MODE == 2) CH += z * sCh;
    if (MODE == 2) auxH += z * sAux;
    if (MODE == 3) auxF += z * sAux;
    if (MODE == 4) bias += (long)z * LL;
    const float* alpha = (MODE == 3) ? (alphaP + (long)z * sAlpha) : nullptr;

    const int tid = threadIdx.x, wid = tid >> 5, lane = tid & 31;
    const int wm = (MT == 128) ? (wid & 1) : 0;
    const int wn = (MT == 128) ? (wid >> 1) : wid;
    const int wnw = (MT == 128) ? 64 : 32;       // warp n width
    const int m0 = blockIdx.y * MT, n0 = blockIdx.x * 128;
    const uint32_t smb = smem_u32(sh);
    const int nk = K >> 5;

    // ---- ldmatrix base addresses (stage 0, k=0), bytes
    uint32_t aAddr[4], bAddr[BP];
    #pragma unroll
    for (int mi = 0; mi < 4; mi++) {
        int off = (wm * 64 + mi * 16 + (lane & 15)) * AST + ((lane >> 4) << 3);
        aAddr[mi] = smb + off * 2;
    }
    #pragma unroll
    for (int p = 0; p < BP; p++) {
        int off;
        if (BKM) // SMEM [n][k]
            off = (wn * wnw + p * 16 + (lane & 7) + ((lane >> 4) << 3)) * BST
                  + (((lane >> 3) & 1) << 3);
        else     // SMEM [k][n]
            off = (lane & 15) * BST + wn * wnw + p * 16 + ((lane >> 4) << 3);
        bAddr[p] = smb + (ASZ2 + off) * 2;
    }

    // ---- stage loader (128 threads)
    auto load_stage = [&](int c) {
        const int slot = c & 3;
        const uint32_t ab = smb + (uint32_t)(slot * STG) * 2;
        const uint32_t bb = ab + ASZ2 * 2;
        #pragma unroll
        for (int i = 0; i < MT / 32; i++) {     // A: MT x 32 halfs
            int v = tid + i * 128;
            int r = v >> 2, ch = v & 3;
            cp16(ab + (uint32_t)(r * AST + ch * 8) * 2,
                 A + (long)(m0 + r) * lda + c * 32 + ch * 8);
        }
        if (BKM) {
            #pragma unroll
            for (int i = 0; i < 4; i++) {       // B: 128 n-rows x 32 halfs
                int v = tid + i * 128;
                int r = v >> 2, ch = v & 3;
                cp16(bb + (uint32_t)(r * BST + ch * 8) * 2,
                     B + (long)(n0 + r) * ldb + c * 32 + ch * 8);
            }
        } else {
            #pragma unroll
            for (int i = 0; i < 4; i++) {       // B: 32 k-rows x 128 halfs
                int v = tid + i * 128;
                int r = v >> 4, ch = v & 15;
                cp16(bb + (uint32_t)(r * BST + ch * 8) * 2,
                     B + (long)(c * 32 + r) * ldb + n0 + ch * 8);
            }
        }
    };

    load_stage(0); cp_commit();
    load_stage(1); cp_commit();
    load_stage(2); cp_commit();

    float acc[4][NI][4] = {};
    for (int c = 0; c < nk; c++) {
        cp_wait<2>();
        __syncthreads();
        if (c + 3 < nk) load_stage(c + 3);
        cp_commit();

        const uint32_t so = (uint32_t)((c & 3) * STG) * 2;
        #pragma unroll
        for (int kk = 0; kk < 2; kk++) {
            const int ks = kk * 16;
            uint32_t af[4][4], bf[NI][2];
            #pragma unroll
            for (int mi = 0; mi < 4; mi++)
                ldm_x4(af[mi], aAddr[mi] + so + ks * 2);
            #pragma unroll
            for (int p = 0; p < BP; p++) {
                uint32_t r4[4];
                if (BKM) ldm_x4(r4, bAddr[p] + so + ks * 2);
                else     ldm_x4_t(r4, bAddr[p] + so + ks * (BST * 2));
                bf[2 * p + 0][0] = r4[0]; bf[2 * p + 0][1] = r4[1];
                bf[2 * p + 1][0] = r4[2]; bf[2 * p + 1][1] = r4[3];
            }
            #pragma unroll
            for (int mi = 0; mi < 4; mi++)
                #pragma unroll
                for (int ni = 0; ni < NI; ni++)
                    mma16816(acc[mi][ni], af[mi], bf[ni]);
        }
    }

    // ---- epilogue
    const int g = lane >> 2, t2 = (lane & 3) << 1;
    #pragma unroll
    for (int mi = 0; mi < 4; mi++) {
        #pragma unroll
        for (int half = 0; half < 2; half++) {
            long r = m0 + wm * 64 + mi * 16 + g + half * 8;
            #pragma unroll
            for (int ni = 0; ni < NI; ni++) {
                int c = n0 + wn * wnw + ni * 8 + t2;
                float v0 = acc[mi][ni][half * 2 + 0];
                float v1 = acc[mi][ni][half * 2 + 1];
                if (MODE == 1) {
                    v0 = siluf(v0 + bias[c]); v1 = siluf(v1 + bias[c + 1]);
                    *(__half2*)(CH + r * (long)ldch + c) = __floats2half2_rn(v0, v1);
                } else if (MODE == 2) {
                    const __half2 gt = *(const __half2*)(auxH + r * (long)ldaux + c);
                    v0 *= __half2float(gt.x); v1 *= __half2float(gt.y);
                    *(__half2*)(CH + r * (long)ldch + c) = __floats2half2_rn(v0, v1);
                } else if (MODE == 3) {
                    const float2 sres = *(const float2*)(auxF + r * (long)ldaux + c);
                    v0 = (v0 + bias[c]) * (1.f + alpha[c]) + sres.x;
                    v1 = (v1 + bias[c + 1]) * (1.f + alpha[c + 1]) + sres.y;
                    *(float2*)(C + r * (long)ldc + c) = make_float2(v0, v1);
                } else {
                    int d0 = (int)r - c;     d0 = d0 < -64 ? -64 : (d0 > 64 ? 64 : d0);
                    int d1 = (int)r - c - 1; d1 = d1 < -64 ? -64 : (d1 > 64 ? 64 : d1);
                    v0 += bias[c] + rel[d0 + 64];
                    v1 += bias[c + 1] + rel[d1 + 64];
                    *(float2*)(C + r * (long)ldc + c) = make_float2(v0, v1);
                }
            }
        }
    }
}

// ---------------- q/k build + RoPE (reads fp16 h) ----------------------------
__global__ void qk_rope_k(const __half* __restrict__ h, const float* __restrict__ mw,
                          const float* __restrict__ mb, const float* __restrict__ scal,
                          __half* __restrict__ q, __half* __restrict__ k) {
    const int row = blockIdx.x;
    const int t   = threadIdx.x;           // 0..127
    const int pos = row & (LL - 1);
    const __half* base = h + (long)row * GVA_N + 2 * PROJ;
    float b0 = __half2float(base[t]), b1 = __half2float(base[t + 128]);
    float q0 = fmaf(b0, mw[t],       mb[t]);
    float q1 = fmaf(b1, mw[t + 128], mb[t + 128]);
    float k0 = fmaf(b0, mw[256 + t],       mb[256 + t]);
    float k1 = fmaf(b1, mw[256 + t + 128], mb[256 + t + 128]);
    float freq = exp2f(-(float)t * (13.287712379549449f / 128.f));
    float ang = (float)pos * freq;
    float sn, cs; sincosf(ang, &sn, &cs);
    float sc = scal[row];
    q[(long)row * 256 + t]       = __float2half_rn((q0 * cs - q1 * sn) * sc);
    q[(long)row * 256 + t + 128] = __float2half_rn((q1 * cs + q0 * sn) * sc);
    k[(long)row * 256 + t]       = __float2half_rn(k0 * cs - k1 * sn);
    k[(long)row * 256 + t + 128] = __float2half_rn(k1 * cs + k0 * sn);
}

// ---------------- row softmax over 1024: fp32 + fp16 outputs -----------------
__global__ __launch_bounds__(256) void softmax_k(float* __restrict__ S,
                                                 __half* __restrict__ S16) {
    float4* p = (float4*)(S + (long)blockIdx.x * LL);
    __half2* p16 = (__half2*)(S16 + (long)blockIdx.x * LL);
    float4 v = p[threadIdx.x];
    __shared__ float rm[8], rs[8];
    float m = fmaxf(fmaxf(v.x, v.y), fmaxf(v.z, v.w));
    m = warpMax(m);
    if ((threadIdx.x & 31) == 0) rm[threadIdx.x >> 5] = m;
    __syncthreads();
    m = rm[0];
    #pragma unroll
    for (int i = 1; i < 8; i++) m = fmaxf(m, rm[i]);
    v.x = __expf(v.x - m); v.y = __expf(v.y - m);
    v.z = __expf(v.z - m); v.w = __expf(v.w - m);
    float s = v.x + v.y + v.z + v.w;
    s = warpSum(s);
    if ((threadIdx.x & 31) == 0) rs[threadIdx.x >> 5] = s;
    __syncthreads();
    s = 0.f;
    #pragma unroll
    for (int i = 0; i < 8; i++) s += rs[i];
    float inv = 1.f / s;
    v.x *= inv; v.y *= inv; v.z *= inv; v.w *= inv;
    p[threadIdx.x] = v;
    p16[threadIdx.x * 2 + 0] = __floats2half2_rn(v.x, v.y);
    p16[threadIdx.x * 2 + 1] = __floats2half2_rn(v.z, v.w);
}

// ---------------- edge = attn[0] + attn[1] (fp32) ----------------------------
__global__ void edge_k(const float* __restrict__ attn, float* __restrict__ e) {
    long i = (long)blockIdx.x * 256 + threadIdx.x;
    float4 a = ((const float4*)attn)[i];
    float4 b = ((const float4*)(attn + (long)LL * LL))[i];
    ((float4*)e)[i] = make_float4(a.x + b.x, a.y + b.y, a.z + b.z, a.w + b.w);
}

// ---------------- launch ------------------------------------------------------
extern "C" void kernel_launch(void* const* d_in, const int* in_sizes, int n_in,
                              void* d_out, int out_size) {
    const float* node      = (const float*)d_in[0];
    const float* qk_scal   = (const float*)d_in[1];
    const float* bias      = (const float*)d_in[2];
    const float* cond      = (const float*)d_in[3];
    const float* w_gva     = (const float*)d_in[4];
    const float* b_gva     = (const float*)d_in[5];
    const float* mhs_w     = (const float*)d_in[6];
    const float* mhs_b     = (const float*)d_in[7];
    const float* relpos    = (const float*)d_in[8];
    const float* w_out     = (const float*)d_in[9];
    const float* b_out     = (const float*)d_in[10];
    const float* w_adaln   = (const float*)d_in[11];
    const float* b_adaln   = (const float*)d_in[12];
    float* out = (float*)d_out;

    float *sc, *part, *gba, *attn, *nodeb;
    __half *x16, *h16, *q16, *k16, *attn16, *av16, *wg16, *wo16;
    cudaGetSymbolAddress((void**)&sc,     d_sc);
    cudaGetSymbolAddress((void**)&part,   d_part);
    cudaGetSymbolAddress((void**)&gba,    d_gba);
    cudaGetSymbolAddress((void**)&x16,    d_x16);
    cudaGetSymbolAddress((void**)&h16,    d_h16);
    cudaGetSymbolAddress((void**)&q16,    d_q16);
    cudaGetSymbolAddress((void**)&k16,    d_k16);
    cudaGetSymbolAddress((void**)&attn,   d_attn);
    cudaGetSymbolAddress((void**)&attn16, d_attn16);
    cudaGetSymbolAddress((void**)&av16,   d_av16);
    cudaGetSymbolAddress((void**)&nodeb,  d_node);
    cudaGetSymbolAddress((void**)&wg16,   d_wgva16);
    cudaGetSymbolAddress((void**)&wo16,   d_wout16);

    const int SMW128 = 4 * (128 * AST + 32 * 136) * 2;   // 75776 (GVA)
    const int SMW64  = 4 * (64 * AST + 32 * 136) * 2;    // 55296 (AV, out-proj)
    const int SMK64  = 4 * (64 * AST + 128 * 40) * 2;    // 61440 (logits)
    cudaFuncSetAttribute(hgemm<1, false, 128>, cudaFuncAttributeMaxDynamicSharedMemorySize, SMW128);
    cudaFuncSetAttribute(hgemm<2, false, 64>,  cudaFuncAttributeMaxDynamicSharedMemorySize, SMW64);
    cudaFuncSetAttribute(hgemm<3, false, 64>,  cudaFuncAttributeMaxDynamicSharedMemorySize, SMW64);
    cudaFuncSetAttribute(hgemm<4, true, 64>,   cudaFuncAttributeMaxDynamicSharedMemorySize, SMK64);

    cudaMemcpyAsync(nodeb, node, (size_t)ROWS * NODE * sizeof(float),
                    cudaMemcpyDeviceToDevice);
    f2h_k<<<(int)((long)NL * NODE * GVA_N / 1024), 256>>>(w_gva, wg16);
    f2h_k<<<(int)((long)NL * PROJ * NODE / 1024), 256>>>(w_out, wo16);

    silu_vec_k<<<(BB * NODE + 255) / 256, 256>>>(cond, sc, BB * NODE);
    adaln_part_k<<<dim3(ADALN_N / 256, BB * KS, NL), 256>>>(sc, w_adaln, part);
    adaln_reduce_k<<<(NL * BB * ADALN_N) / 256, 256>>>(part, b_adaln, gba);

    for (int l = 0; l < NL; l++) {
        const float* gba_l = gba + (long)l * BB * ADALN_N;

        ln_mod_k<<<ROWS, 256>>>(nodeb, gba_l, x16);

        // h16 = silu(x @ w_gva + b_gva)   [2048 x 5376 x 1280]
        hgemm<1, false, 128><<<dim3(GVA_N / 128, ROWS / 128, 1), 128, SMW128>>>(
            NODE,
            x16, NODE, 0L,
            wg16 + (long)l * NODE * GVA_N, GVA_N, 0L,
            nullptr, 0, 0L,
            h16, GVA_N, 0L,
            b_gva + l * GVA_N,
            nullptr, 0, 0L, nullptr, nullptr, 0, nullptr);

        qk_rope_k<<<ROWS, 128>>>(h16, mhs_w + l * 2 * ATTND, mhs_b + l * 2 * ATTND,
                                 qk_scal, q16, k16);

        // logits = q @ k^T + bias + rel   [1024 x 1024 x 256] x2, MT=64
        hgemm<4, true, 64><<<dim3(LL / 128, LL / 64, BB), 128, SMK64>>>(
            ATTND,
            q16, ATTND, (long)LL * ATTND,
            k16, ATTND, (long)LL * ATTND,
            attn, LL, (long)LL * LL,
            nullptr, 0, 0L,
            bias,
            nullptr, 0, 0L, nullptr, nullptr, 0,
            relpos + l * NREL);

        softmax_k<<<ROWS, 256>>>(attn, attn16);

        if (l == NL - 1)
            edge_k<<<(LL * LL / 4) / 256, 256>>>(attn, out + (long)ROWS * NODE);

        // av16 = (attn @ values) * gates   [1024 x 2560 x 1024] x2, MT=64
        hgemm<2, false, 64><<<dim3(PROJ / 128, LL / 64, BB), 128, SMW64>>>(
            LL,
            attn16, LL, (long)LL * LL,
            h16 + PROJ, GVA_N, (long)LL * GVA_N,
            nullptr, 0, 0L,
            av16, PROJ, (long)LL * PROJ,
            nullptr,
            h16, GVA_N, (long)LL * GVA_N,    // gates fp16
            nullptr, nullptr, 0, nullptr);

        // node = (av @ w_out + b_out)*(1+alpha) + shortcut  [1024 x 1280 x 2560] x2, MT=64
        float* Cdst = (l == NL - 1) ? out : nodeb;
        hgemm<3, false, 64><<<dim3(NODE / 128, LL / 64, BB), 128, SMW64>>>(
            PROJ,
            av16, PROJ, (long)LL * PROJ,
            wo16 + (long)l * PROJ * NODE, NODE, 0L,
            Cdst, NODE, (long)LL * NODE,
            nullptr, 0, 0L,
            b_out + l * NODE,
            nullptr, NODE, (long)LL * NODE,
            nodeb,                            // residual fp32
            gba_l + 2 * NODE, ADALN_N, nullptr);
    }
    (void)in_sizes; (void)n_in; (void)out_size;
}

// round 10
// speedup vs baseline: 7.7802x; 1.0125x over previous
#include <cuda_runtime.h>
#include <cuda_fp16.h>
#include <cstdint>
#include <math.h>

#define NODE   1280
#define PROJ   2560
#define ATTND  256
#define NREL   129
#define NL     4
#define BB     2
#define LL     1024
#define GVA_N  (2*PROJ + ATTND)   // 5376
#define ADALN_N (3*NODE)          // 3840
#define ROWS   (BB*LL)            // 2048
#define KS     10                 // adaLN split-K factor

// ---------------- scratch (device globals; no allocation allowed) ----------
__device__ float  d_sc    [BB*NODE];
__device__ float  d_part  [NL*BB*KS*ADALN_N];
__device__ float  d_gba   [NL*BB*ADALN_N];
__device__ __half d_x16   [ROWS*NODE];
__device__ __half d_h16   [ROWS*GVA_N];
__device__ __half d_q16   [ROWS*ATTND];
__device__ __half d_k16   [ROWS*ATTND];
__device__ float  d_attn  [(long)BB*LL*LL];
__device__ __half d_attn16[(long)BB*LL*LL];
__device__ __half d_av16  [ROWS*PROJ];
__device__ float  d_node  [ROWS*NODE];
__device__ __half d_wgva16[(long)NL*NODE*GVA_N];
__device__ __half d_wout16[(long)NL*PROJ*NODE];

// ---------------- helpers ---------------------------------------------------
__device__ __forceinline__ float siluf(float x) { return x / (1.f + __expf(-x)); }
__device__ __forceinline__ float warpMax(float v) {
    #pragma unroll
    for (int o = 16; o > 0; o >>= 1) v = fmaxf(v, __shfl_xor_sync(0xffffffffu, v, o));
    return v;
}
__device__ __forceinline__ float warpSum(float v) {
    #pragma unroll
    for (int o = 16; o > 0; o >>= 1) v += __shfl_xor_sync(0xffffffffu, v, o);
    return v;
}
__device__ __forceinline__ uint32_t smem_u32(const void* p) {
    uint32_t a;
    asm("{ .reg .u64 t; cvta.to.shared.u64 t, %1; cvt.u32.u64 %0, t; }"
        : "=r"(a) : "l"(p));
    return a;
}
__device__ __forceinline__ void cp16(uint32_t dst, const void* src) {
    asm volatile("cp.async.cg.shared.global [%0], [%1], 16;" :: "r"(dst), "l"(src));
}
__device__ __forceinline__ void cp_commit() {
    asm volatile("cp.async.commit_group;" ::: "memory");
}
template <int N>
__device__ __forceinline__ void cp_wait() {
    asm volatile("cp.async.wait_group %0;" :: "n"(N) : "memory");
}
__device__ __forceinline__ void ldm_x4(uint32_t* r, uint32_t a) {
    asm volatile("ldmatrix.sync.aligned.m8n8.x4.shared.b16 {%0,%1,%2,%3}, [%4];"
                 : "=r"(r[0]), "=r"(r[1]), "=r"(r[2]), "=r"(r[3]) : "r"(a));
}
__device__ __forceinline__ void ldm_x4_t(uint32_t* r, uint32_t a) {
    asm volatile("ldmatrix.sync.aligned.m8n8.x4.trans.shared.b16 {%0,%1,%2,%3}, [%4];"
                 : "=r"(r[0]), "=r"(r[1]), "=r"(r[2]), "=r"(r[3]) : "r"(a));
}
__device__ __forceinline__ void mma16816(float* c, const uint32_t* a, const uint32_t* b) {
    asm volatile(
        "mma.sync.aligned.m16n8k16.row.col.f32.f16.f16.f32 "
        "{%0,%1,%2,%3}, {%4,%5,%6,%7}, {%8,%9}, {%0,%1,%2,%3};"
        : "+f"(c[0]), "+f"(c[1]), "+f"(c[2]), "+f"(c[3])
        : "r"(a[0]), "r"(a[1]), "r"(a[2]), "r"(a[3]), "r"(b[0]), "r"(b[1]));
}

// ---------------- small kernels ---------------------------------------------
__global__ void silu_vec_k(const float* __restrict__ c, float* __restrict__ sc, int n) {
    int i = blockIdx.x * 256 + threadIdx.x;
    if (i < n) sc[i] = siluf(c[i]);
}

__global__ void f2h_k(const float* __restrict__ in, __half* __restrict__ out) {
    long i = (long)blockIdx.x * 256 + threadIdx.x;
    float4 v = ((const float4*)in)[i];
    ((__half2*)out)[2 * i]     = __floats2half2_rn(v.x, v.y);
    ((__half2*)out)[2 * i + 1] = __floats2half2_rn(v.z, v.w);
}

__global__ void adaln_part_k(const float* __restrict__ sc, const float* __restrict__ w,
                             float* __restrict__ part) {
    const int l = blockIdx.z;
    const int b = blockIdx.y / KS, ks = blockIdx.y % KS;
    const int col = blockIdx.x * 256 + threadIdx.x;
    const int KC = NODE / KS;                  // 128
    const float* s  = sc + b * NODE + ks * KC;
    const float* wp = w + (long)l * NODE * ADALN_N + (long)ks * KC * ADALN_N + col;
    float a0 = 0.f, a1 = 0.f;
    #pragma unroll 8
    for (int k = 0; k < KC; k += 2) {
        a0 = fmaf(s[k],     wp[(long)k * ADALN_N],       a0);
        a1 = fmaf(s[k + 1], wp[(long)(k + 1) * ADALN_N], a1);
    }
    part[((((long)l * BB) + b) * KS + ks) * ADALN_N + col] = a0 + a1;
}
__global__ void adaln_reduce_k(const float* __restrict__ part,
                               const float* __restrict__ bvec, float* __restrict__ gba) {
    long idx = (long)blockIdx.x * 256 + threadIdx.x;
    int l = (int)(idx / (BB * ADALN_N));
    int rem = (int)(idx % (BB * ADALN_N));
    int b = rem / ADALN_N, col = rem % ADALN_N;
    const float* p = part + (((long)l * BB + b) * KS) * ADALN_N + col;
    float acc = bvec[l * ADALN_N + col];
    #pragma unroll
    for (int i = 0; i < KS; i++) acc += p[(long)i * ADALN_N];
    gba[idx] = acc;
}

// LayerNorm + modulate -> fp16 x
__global__ __launch_bounds__(256) void ln_mod_k(const float* __restrict__ node,
                                                const float* __restrict__ gba,
                                                __half* __restrict__ x16) {
    const int row = blockIdx.x;
    const int b   = row >> 10;
    const float* p = node + (long)row * NODE;
    float vals[5];
    float s = 0.f, sq = 0.f;
    #pragma unroll
    for (int i = 0; i < 5; i++) {
        float v = p[threadIdx.x + i * 256];
        vals[i] = v; s += v; sq += v * v;
    }
    __shared__ float rs[8], rq[8];
    s = warpSum(s); sq = warpSum(sq);
    if ((threadIdx.x & 31) == 0) { rs[threadIdx.x >> 5] = s; rq[threadIdx.x >> 5] = sq; }
    __syncthreads();
    float ts = 0.f, tq = 0.f;
    #pragma unroll
    for (int i = 0; i < 8; i++) { ts += rs[i]; tq += rq[i]; }
    const float mean = ts * (1.f / NODE);
    const float var  = tq * (1.f / NODE) - mean * mean;
    const float rstd = rsqrtf(var + 1e-5f);
    const float* g = gba + (long)b * ADALN_N;
    __half* xo = x16 + (long)row * NODE;
    #pragma unroll
    for (int i = 0; i < 5; i++) {
        int c = threadIdx.x + i * 256;
        float v = (vals[i] - mean) * rstd;
        xo[c] = __float2half_rn(v * (1.f + g[c]) + g[NODE + c]);
    }
}

// ============================================================================
// fp16 mma.sync GEMM.
//  MT=128: 256 threads, 8 warps, warp tile 64x32, occ 2 -> 16 warps/SM
//  MT=64 : 128 threads, 4 warps, warp tile 64x32, occ 3
// BK=32, 4-stage cp.async pipeline, ldmatrix fragments, fp32 accum.
// A: fp16 [M,K] row-major.
// B: BKM=false -> fp16 [K,N] row-major; SMEM [k][n], ldmatrix.trans
//    BKM=true  -> fp16 [N,K] row-major; SMEM [n][k], ldmatrix
// MODE 1: CH = silu(acc + bias[n])                 (fp16 out)
// MODE 2: CH = acc * auxH[m,n]                     (fp16 out)
// MODE 3: C  = (acc + bias[n])*(1+alpha[n]) + auxF (fp32 out)
// MODE 4: C  = acc + bias[z,n] + rel[clamp(m-n)]   (fp32 out)
// ============================================================================
#define AST 40              // A row stride (halfs)

template <int MODE, bool BKM, int MT>
__global__ __launch_bounds__((MT == 128 ? 256 : 128), (MT == 128 ? 2 : 3)) void hgemm(
    int K,
    const __half* __restrict__ A, int lda, long sA,
    const __half* __restrict__ B, int ldb, long sB,
    float* __restrict__ C, int ldc, long sC,
    __half* __restrict__ CH, int ldch, long sCh,
    const float* __restrict__ bias,
    const __half* __restrict__ auxH, int ldaux, long sAux,
    const float* __restrict__ auxF,
    const float* __restrict__ alphaP, int sAlpha,
    const float* __restrict__ rel) {
    constexpr int THREADS = (MT == 128) ? 256 : 128;
    constexpr int BST = BKM ? 40 : 136;
    constexpr int BSZ = BKM ? 128 * 40 : 32 * 136;
    constexpr int ASZ2 = MT * AST;               // A halfs per stage
    constexpr int STG = ASZ2 + BSZ;              // halfs per stage
    constexpr int AITER = (MT * 4) / THREADS;    // A 16B copies per thread
    constexpr int BITER = 512 / THREADS;         // B 16B copies per thread

    extern __shared__ __half sh[];
    const int z = blockIdx.z;
    A += z * sA; B += z * sB;
    if (MODE == 3 || MODE == 4) C += z * sC;
    if (MODE == 1 || MODE == 2) CH += z * sCh;
    if (MODE == 2) auxH += z * sAux;
    if (MODE == 3) auxF += z * sAux;
    if (MODE == 4) bias += (long)z * LL;
    const float* alpha = (MODE == 3) ? (alphaP + (long)z * sAlpha) : nullptr;

    const int tid = threadIdx.x, wid = tid >> 5, lane = tid & 31;
    const int wm = (MT == 128) ? (wid & 1) : 0;     // m warp (x64 rows)
    const int wn = (MT == 128) ? (wid >> 1) : wid;  // n warp (x32 cols)
    const int m0 = blockIdx.y * MT, n0 = blockIdx.x * 128;
    const uint32_t smb = smem_u32(sh);
    const int nk = K >> 5;

    // ---- ldmatrix base addresses (stage 0, k=0), bytes
    uint32_t aAddr[4], bAddr[2];
    #pragma unroll
    for (int mi = 0; mi < 4; mi++) {
        int off = (wm * 64 + mi * 16 + (lane & 15)) * AST + ((lane >> 4) << 3);
        aAddr[mi] = smb + off * 2;
    }
    #pragma unroll
    for (int p = 0; p < 2; p++) {
        int off;
        if (BKM) // SMEM [n][k]
            off = (wn * 32 + p * 16 + (lane & 7) + ((lane >> 4) << 3)) * BST
                  + (((lane >> 3) & 1) << 3);
        else     // SMEM [k][n]
            off = (lane & 15) * BST + wn * 32 + p * 16 + ((lane >> 4) << 3);
        bAddr[p] = smb + (ASZ2 + off) * 2;
    }

    // ---- stage loader
    auto load_stage = [&](int c) {
        const int slot = c & 3;
        const uint32_t ab = smb + (uint32_t)(slot * STG) * 2;
        const uint32_t bb = ab + ASZ2 * 2;
        #pragma unroll
        for (int i = 0; i < AITER; i++) {                    // A: MT x 32 halfs
            int v = tid + i * THREADS;
            int r = v >> 2, ch = v & 3;
            cp16(ab + (uint32_t)(r * AST + ch * 8) * 2,
                 A + (long)(m0 + r) * lda + c * 32 + ch * 8);
        }
        if (BKM) {
            #pragma unroll
            for (int i = 0; i < BITER; i++) {                // B: 128 n-rows x 32 halfs
                int v = tid + i * THREADS;
                int r = v >> 2, ch = v & 3;
                cp16(bb + (uint32_t)(r * BST + ch * 8) * 2,
                     B + (long)(n0 + r) * ldb + c * 32 + ch * 8);
            }
        } else {
            #pragma unroll
            for (int i = 0; i < BITER; i++) {                // B: 32 k-rows x 128 halfs
                int v = tid + i * THREADS;
                int r = v >> 4, ch = v & 15;
                cp16(bb + (uint32_t)(r * BST + ch * 8) * 2,
                     B + (long)(c * 32 + r) * ldb + n0 + ch * 8);
            }
        }
    };

    load_stage(0); cp_commit();
    load_stage(1); cp_commit();
    load_stage(2); cp_commit();

    float acc[4][4][4] = {};
    for (int c = 0; c < nk; c++) {
        cp_wait<2>();
        __syncthreads();
        if (c + 3 < nk) load_stage(c + 3);
        cp_commit();

        const uint32_t so = (uint32_t)((c & 3) * STG) * 2;
        #pragma unroll
        for (int kk = 0; kk < 2; kk++) {
            const int ks = kk * 16;
            uint32_t af[4][4], bf[4][2];
            #pragma unroll
            for (int mi = 0; mi < 4; mi++)
                ldm_x4(af[mi], aAddr[mi] + so + ks * 2);
            #pragma unroll
            for (int p = 0; p < 2; p++) {
                uint32_t r4[4];
                if (BKM) ldm_x4(r4, bAddr[p] + so + ks * 2);
                else     ldm_x4_t(r4, bAddr[p] + so + ks * (BST * 2));
                bf[2 * p + 0][0] = r4[0]; bf[2 * p + 0][1] = r4[1];
                bf[2 * p + 1][0] = r4[2]; bf[2 * p + 1][1] = r4[3];
            }
            #pragma unroll
            for (int mi = 0; mi < 4; mi++)
                #pragma unroll
                for (int ni = 0; ni < 4; ni++)
                    mma16816(acc[mi][ni], af[mi], bf[ni]);
        }
    }

    // ---- epilogue
    const int g = lane >> 2, t2 = (lane & 3) << 1;
    #pragma unroll
    for (int mi = 0; mi < 4; mi++) {
        #pragma unroll
        for (int half = 0; half < 2; half++) {
            long r = m0 + wm * 64 + mi * 16 + g + half * 8;
            #pragma unroll
            for (int ni = 0; ni < 4; ni++) {
                int c = n0 + wn * 32 + ni * 8 + t2;
                float v0 = acc[mi][ni][half * 2 + 0];
                float v1 = acc[mi][ni][half * 2 + 1];
                if (MODE == 1) {
                    v0 = siluf(v0 + bias[c]); v1 = siluf(v1 + bias[c + 1]);
                    *(__half2*)(CH + r * (long)ldch + c) = __floats2half2_rn(v0, v1);
                } else if (MODE == 2) {
                    const __half2 gt = *(const __half2*)(auxH + r * (long)ldaux + c);
                    v0 *= __half2float(gt.x); v1 *= __half2float(gt.y);
                    *(__half2*)(CH + r * (long)ldch + c) = __floats2half2_rn(v0, v1);
                } else if (MODE == 3) {
                    const float2 sres = *(const float2*)(auxF + r * (long)ldaux + c);
                    v0 = (v0 + bias[c]) * (1.f + alpha[c]) + sres.x;
                    v1 = (v1 + bias[c + 1]) * (1.f + alpha[c + 1]) + sres.y;
                    *(float2*)(C + r * (long)ldc + c) = make_float2(v0, v1);
                } else {
                    int d0 = (int)r - c;     d0 = d0 < -64 ? -64 : (d0 > 64 ? 64 : d0);
                    int d1 = (int)r - c - 1; d1 = d1 < -64 ? -64 : (d1 > 64 ? 64 : d1);
                    v0 += bias[c] + rel[d0 + 64];
                    v1 += bias[c + 1] + rel[d1 + 64];
                    *(float2*)(C + r * (long)ldc + c) = make_float2(v0, v1);
                }
            }
        }
    }
}

// ---------------- q/k build + RoPE (reads fp16 h) ----------------------------
__global__ void qk_rope_k(const __half* __restrict__ h, const float* __restrict__ mw,
                          const float* __restrict__ mb, const float* __restrict__ scal,
                          __half* __restrict__ q, __half* __restrict__ k) {
    const int row = blockIdx.x;
    const int t   = threadIdx.x;           // 0..127
    const int pos = row & (LL - 1);
    const __half* base = h + (long)row * GVA_N + 2 * PROJ;
    float b0 = __half2float(base[t]), b1 = __half2float(base[t + 128]);
    float q0 = fmaf(b0, mw[t],       mb[t]);
    float q1 = fmaf(b1, mw[t + 128], mb[t + 128]);
    float k0 = fmaf(b0, mw[256 + t],       mb[256 + t]);
    float k1 = fmaf(b1, mw[256 + t + 128], mb[256 + t + 128]);
    float freq = exp2f(-(float)t * (13.287712379549449f / 128.f));
    float ang = (float)pos * freq;
    float sn, cs; sincosf(ang, &sn, &cs);
    float sc = scal[row];
    q[(long)row * 256 + t]       = __float2half_rn((q0 * cs - q1 * sn) * sc);
    q[(long)row * 256 + t + 128] = __float2half_rn((q1 * cs + q0 * sn) * sc);
    k[(long)row * 256 + t]       = __float2half_rn(k0 * cs - k1 * sn);
    k[(long)row * 256 + t + 128] = __float2half_rn(k1 * cs + k0 * sn);
}

// ---------------- row softmax over 1024: fp16 out, fp32 out optional ---------
__global__ __launch_bounds__(256) void softmax_k(float* __restrict__ S,
                                                 __half* __restrict__ S16,
                                                 int write32) {
    float4* p = (float4*)(S + (long)blockIdx.x * LL);
    __half2* p16 = (__half2*)(S16 + (long)blockIdx.x * LL);
    float4 v = p[threadIdx.x];
    __shared__ float rm[8], rs[8];
    float m = fmaxf(fmaxf(v.x, v.y), fmaxf(v.z, v.w));
    m = warpMax(m);
    if ((threadIdx.x & 31) == 0) rm[threadIdx.x >> 5] = m;
    __syncthreads();
    m = rm[0];
    #pragma unroll
    for (int i = 1; i < 8; i++) m = fmaxf(m, rm[i]);
    v.x = __expf(v.x - m); v.y = __expf(v.y - m);
    v.z = __expf(v.z - m); v.w = __expf(v.w - m);
    float s = v.x + v.y + v.z + v.w;
    s = warpSum(s);
    if ((threadIdx.x & 31) == 0) rs[threadIdx.x >> 5] = s;
    __syncthreads();
    s = 0.f;
    #pragma unroll
    for (int i = 0; i < 8; i++) s += rs[i];
    float inv = 1.f / s;
    v.x *= inv; v.y *= inv; v.z *= inv; v.w *= inv;
    if (write32) p[threadIdx.x] = v;
    p16[threadIdx.x * 2 + 0] = __floats2half2_rn(v.x, v.y);
    p16[threadIdx.x * 2 + 1] = __floats2half2_rn(v.z, v.w);
}

// ---------------- edge = attn[0] + attn[1] (fp32) ----------------------------
__global__ void edge_k(const float* __restrict__ attn, float* __restrict__ e) {
    long i = (long)blockIdx.x * 256 + threadIdx.x;
    float4 a = ((const float4*)attn)[i];
    float4 b = ((const float4*)(attn + (long)LL * LL))[i];
    ((float4*)e)[i] = make_float4(a.x + b.x, a.y + b.y, a.z + b.z, a.w + b.w);
}

// ---------------- launch ------------------------------------------------------
extern "C" void kernel_launch(void* const* d_in, const int* in_sizes, int n_in,
                              void* d_out, int out_size) {
    const float* node      = (const float*)d_in[0];
    const float* qk_scal   = (const float*)d_in[1];
    const float* bias      = (const float*)d_in[2];
    const float* cond      = (const float*)d_in[3];
    const float* w_gva     = (const float*)d_in[4];
    const float* b_gva     = (const float*)d_in[5];
    const float* mhs_w     = (const float*)d_in[6];
    const float* mhs_b     = (const float*)d_in[7];
    const float* relpos    = (const float*)d_in[8];
    const float* w_out     = (const float*)d_in[9];
    const float* b_out     = (const float*)d_in[10];
    const float* w_adaln   = (const float*)d_in[11];
    const float* b_adaln   = (const float*)d_in[12];
    float* out = (float*)d_out;

    float *sc, *part, *gba, *attn, *nodeb;
    __half *x16, *h16, *q16, *k16, *attn16, *av16, *wg16, *wo16;
    cudaGetSymbolAddress((void**)&sc,     d_sc);
    cudaGetSymbolAddress((void**)&part,   d_part);
    cudaGetSymbolAddress((void**)&gba,    d_gba);
    cudaGetSymbolAddress((void**)&x16,    d_x16);
    cudaGetSymbolAddress((void**)&h16,    d_h16);
    cudaGetSymbolAddress((void**)&q16,    d_q16);
    cudaGetSymbolAddress((void**)&k16,    d_k16);
    cudaGetSymbolAddress((void**)&attn,   d_attn);
    cudaGetSymbolAddress((void**)&attn16, d_attn16);
    cudaGetSymbolAddress((void**)&av16,   d_av16);
    cudaGetSymbolAddress((void**)&nodeb,  d_node);
    cudaGetSymbolAddress((void**)&wg16,   d_wgva16);
    cudaGetSymbolAddress((void**)&wo16,   d_wout16);

    const int SMW128 = 4 * (128 * AST + 32 * 136) * 2;   // 75776 (GVA, AV)
    const int SMW64  = 4 * (64 * AST + 32 * 136) * 2;    // 55296 (out-proj)
    const int SMK64  = 4 * (64 * AST + 128 * 40) * 2;    // 61440 (logits)
    cudaFuncSetAttribute(hgemm<1, false, 128>, cudaFuncAttributeMaxDynamicSharedMemorySize, SMW128);
    cudaFuncSetAttribute(hgemm<2, false, 128>, cudaFuncAttributeMaxDynamicSharedMemorySize, SMW128);
    cudaFuncSetAttribute(hgemm<3, false, 64>,  cudaFuncAttributeMaxDynamicSharedMemorySize, SMW64);
    cudaFuncSetAttribute(hgemm<4, true, 64>,   cudaFuncAttributeMaxDynamicSharedMemorySize, SMK64);

    cudaMemcpyAsync(nodeb, node, (size_t)ROWS * NODE * sizeof(float),
                    cudaMemcpyDeviceToDevice);
    f2h_k<<<(int)((long)NL * NODE * GVA_N / 1024), 256>>>(w_gva, wg16);
    f2h_k<<<(int)((long)NL * PROJ * NODE / 1024), 256>>>(w_out, wo16);

    silu_vec_k<<<(BB * NODE + 255) / 256, 256>>>(cond, sc, BB * NODE);
    adaln_part_k<<<dim3(ADALN_N / 256, BB * KS, NL), 256>>>(sc, w_adaln, part);
    adaln_reduce_k<<<(NL * BB * ADALN_N) / 256, 256>>>(part, b_adaln, gba);

    for (int l = 0; l < NL; l++) {
        const float* gba_l = gba + (long)l * BB * ADALN_N;

        ln_mod_k<<<ROWS, 256>>>(nodeb, gba_l, x16);

        // h16 = silu(x @ w_gva + b_gva)   [2048 x 5376 x 1280], 256 threads
        hgemm<1, false, 128><<<dim3(GVA_N / 128, ROWS / 128, 1), 256, SMW128>>>(
            NODE,
            x16, NODE, 0L,
            wg16 + (long)l * NODE * GVA_N, GVA_N, 0L,
            nullptr, 0, 0L,
            h16, GVA_N, 0L,
            b_gva + l * GVA_N,
            nullptr, 0, 0L, nullptr, nullptr, 0, nullptr);

        qk_rope_k<<<ROWS, 128>>>(h16, mhs_w + l * 2 * ATTND, mhs_b + l * 2 * ATTND,
                                 qk_scal, q16, k16);

        // logits = q @ k^T + bias + rel   [1024 x 1024 x 256] x2, MT=64
        hgemm<4, true, 64><<<dim3(LL / 128, LL / 64, BB), 128, SMK64>>>(
            ATTND,
            q16, ATTND, (long)LL * ATTND,
            k16, ATTND, (long)LL * ATTND,
            attn, LL, (long)LL * LL,
            nullptr, 0, 0L,
            bias,
            nullptr, 0, 0L, nullptr, nullptr, 0,
            relpos + l * NREL);

        softmax_k<<<ROWS, 256>>>(attn, attn16, (l == NL - 1) ? 1 : 0);

        if (l == NL - 1)
            edge_k<<<(LL * LL / 4) / 256, 256>>>(attn, out + (long)ROWS * NODE);

        // av16 = (attn @ values) * gates   [1024 x 2560 x 1024] x2, MT=128, 256 thr
        hgemm<2, false, 128><<<dim3(PROJ / 128, LL / 128, BB), 256, SMW128>>>(
            LL,
            attn16, LL, (long)LL * LL,
            h16 + PROJ, GVA_N, (long)LL * GVA_N,
            nullptr, 0, 0L,
            av16, PROJ, (long)LL * PROJ,
            nullptr,
            h16, GVA_N, (long)LL * GVA_N,    // gates fp16
            nullptr, nullptr, 0, nullptr);

        // node = (av @ w_out + b_out)*(1+alpha) + shortcut  [1024 x 1280 x 2560] x2, MT=64
        float* Cdst = (l == NL - 1) ? out : nodeb;
        hgemm<3, false, 64><<<dim3(NODE / 128, LL / 64, BB), 128, SMW64>>>(
            PROJ,
            av16, PROJ, (long)LL * PROJ,
            wo16 + (long)l * PROJ * NODE, NODE, 0L,
            Cdst, NODE, (long)LL * NODE,
            nullptr, 0, 0L,
            b_out + l * NODE,
            nullptr, NODE, (long)LL * NODE,
            nodeb,                            // residual fp32
            gba_l + 2 * NODE, ADALN_N, nullptr);
    }
    (void)in_sizes; (void)n_in; (void)out_size;
}

// round 11
// speedup vs baseline: 8.2065x; 1.0548x over previous
#include <cuda_runtime.h>
#include <cuda_fp16.h>
#include <cstdint>
#include <math.h>

#define NODE   1280
#define PROJ   2560
#define ATTND  256
#define NREL   129
#define NL     4
#define BB     2
#define LL     1024
#define GVA_N  (2*PROJ + ATTND)   // 5376
#define ADALN_N (3*NODE)          // 3840
#define ROWS   (BB*LL)            // 2048
#define KS     10                 // adaLN split-K factor

// ---------------- scratch (device globals; no allocation allowed) ----------
__device__ float  d_sc    [BB*NODE];
__device__ float  d_part  [NL*BB*KS*ADALN_N];
__device__ float  d_gba   [NL*BB*ADALN_N];
__device__ __half d_x16   [ROWS*NODE];
__device__ __half d_h16   [ROWS*GVA_N];
__device__ __half d_q16   [ROWS*ATTND];
__device__ __half d_k16   [ROWS*ATTND];
__device__ float  d_attn  [(long)BB*LL*LL];
__device__ __half d_attn16[(long)BB*LL*LL];
__device__ __half d_av16  [ROWS*PROJ];
__device__ float  d_node  [ROWS*NODE];
__device__ __half d_wgva16[(long)NL*NODE*GVA_N];
__device__ __half d_wout16[(long)NL*PROJ*NODE];

// ---------------- helpers ---------------------------------------------------
__device__ __forceinline__ float siluf(float x) { return x / (1.f + __expf(-x)); }
__device__ __forceinline__ float warpMax(float v) {
    #pragma unroll
    for (int o = 16; o > 0; o >>= 1) v = fmaxf(v, __shfl_xor_sync(0xffffffffu, v, o));
    return v;
}
__device__ __forceinline__ float warpSum(float v) {
    #pragma unroll
    for (int o = 16; o > 0; o >>= 1) v += __shfl_xor_sync(0xffffffffu, v, o);
    return v;
}
__device__ __forceinline__ uint32_t smem_u32(const void* p) {
    uint32_t a;
    asm("{ .reg .u64 t; cvta.to.shared.u64 t, %1; cvt.u32.u64 %0, t; }"
        : "=r"(a) : "l"(p));
    return a;
}
__device__ __forceinline__ void cp16(uint32_t dst, const void* src) {
    asm volatile("cp.async.cg.shared.global [%0], [%1], 16;" :: "r"(dst), "l"(src));
}
__device__ __forceinline__ void cp_commit() {
    asm volatile("cp.async.commit_group;" ::: "memory");
}
template <int N>
__device__ __forceinline__ void cp_wait() {
    asm volatile("cp.async.wait_group %0;" :: "n"(N) : "memory");
}
__device__ __forceinline__ void ldm_x4(uint32_t* r, uint32_t a) {
    asm volatile("ldmatrix.sync.aligned.m8n8.x4.shared.b16 {%0,%1,%2,%3}, [%4];"
                 : "=r"(r[0]), "=r"(r[1]), "=r"(r[2]), "=r"(r[3]) : "r"(a));
}
__device__ __forceinline__ void ldm_x4_t(uint32_t* r, uint32_t a) {
    asm volatile("ldmatrix.sync.aligned.m8n8.x4.trans.shared.b16 {%0,%1,%2,%3}, [%4];"
                 : "=r"(r[0]), "=r"(r[1]), "=r"(r[2]), "=r"(r[3]) : "r"(a));
}
__device__ __forceinline__ void mma16816(float* c, const uint32_t* a, const uint32_t* b) {
    asm volatile(
        "mma.sync.aligned.m16n8k16.row.col.f32.f16.f16.f32 "
        "{%0,%1,%2,%3}, {%4,%5,%6,%7}, {%8,%9}, {%0,%1,%2,%3};"
        : "+f"(c[0]), "+f"(c[1]), "+f"(c[2]), "+f"(c[3])
        : "r"(a[0]), "r"(a[1]), "r"(a[2]), "r"(a[3]), "r"(b[0]), "r"(b[1]));
}

// ---------------- small kernels ---------------------------------------------
__global__ void silu_vec_k(const float* __restrict__ c, float* __restrict__ sc, int n) {
    int i = blockIdx.x * 256 + threadIdx.x;
    if (i < n) sc[i] = siluf(c[i]);
}

__global__ void f2h_k(const float* __restrict__ in, __half* __restrict__ out) {
    long i = (long)blockIdx.x * 256 + threadIdx.x;
    float4 v = ((const float4*)in)[i];
    ((__half2*)out)[2 * i]     = __floats2half2_rn(v.x, v.y);
    ((__half2*)out)[2 * i + 1] = __floats2half2_rn(v.z, v.w);
}

__global__ void adaln_part_k(const float* __restrict__ sc, const float* __restrict__ w,
                             float* __restrict__ part) {
    const int l = blockIdx.z;
    const int b = blockIdx.y / KS, ks = blockIdx.y % KS;
    const int col = blockIdx.x * 256 + threadIdx.x;
    const int KC = NODE / KS;                  // 128
    const float* s  = sc + b * NODE + ks * KC;
    const float* wp = w + (long)l * NODE * ADALN_N + (long)ks * KC * ADALN_N + col;
    float a0 = 0.f, a1 = 0.f;
    #pragma unroll 8
    for (int k = 0; k < KC; k += 2) {
        a0 = fmaf(s[k],     wp[(long)k * ADALN_N],       a0);
        a1 = fmaf(s[k + 1], wp[(long)(k + 1) * ADALN_N], a1);
    }
    part[((((long)l * BB) + b) * KS + ks) * ADALN_N + col] = a0 + a1;
}
__global__ void adaln_reduce_k(const float* __restrict__ part,
                               const float* __restrict__ bvec, float* __restrict__ gba) {
    long idx = (long)blockIdx.x * 256 + threadIdx.x;
    int l = (int)(idx / (BB * ADALN_N));
    int rem = (int)(idx % (BB * ADALN_N));
    int b = rem / ADALN_N, col = rem % ADALN_N;
    const float* p = part + (((long)l * BB + b) * KS) * ADALN_N + col;
    float acc = bvec[l * ADALN_N + col];
    #pragma unroll
    for (int i = 0; i < KS; i++) acc += p[(long)i * ADALN_N];
    gba[idx] = acc;
}

// LayerNorm + modulate -> fp16 x
__global__ __launch_bounds__(256) void ln_mod_k(const float* __restrict__ node,
                                                const float* __restrict__ gba,
                                                __half* __restrict__ x16) {
    const int row = blockIdx.x;
    const int b   = row >> 10;
    const float* p = node + (long)row * NODE;
    float vals[5];
    float s = 0.f, sq = 0.f;
    #pragma unroll
    for (int i = 0; i < 5; i++) {
        float v = p[threadIdx.x + i * 256];
        vals[i] = v; s += v; sq += v * v;
    }
    __shared__ float rs[8], rq[8];
    s = warpSum(s); sq = warpSum(sq);
    if ((threadIdx.x & 31) == 0) { rs[threadIdx.x >> 5] = s; rq[threadIdx.x >> 5] = sq; }
    __syncthreads();
    float ts = 0.f, tq = 0.f;
    #pragma unroll
    for (int i = 0; i < 8; i++) { ts += rs[i]; tq += rq[i]; }
    const float mean = ts * (1.f / NODE);
    const float var  = tq * (1.f / NODE) - mean * mean;
    const float rstd = rsqrtf(var + 1e-5f);
    const float* g = gba + (long)b * ADALN_N;
    __half* xo = x16 + (long)row * NODE;
    #pragma unroll
    for (int i = 0; i < 5; i++) {
        int c = threadIdx.x + i * 256;
        float v = (vals[i] - mean) * rstd;
        xo[c] = __float2half_rn(v * (1.f + g[c]) + g[NODE + c]);
    }
}

// ============================================================================
// fp16 mma.sync GEMM: CTA tile 64x128, 128 threads (4 warps, 64x32 warp tile),
// BK=32, 3-stage cp.async pipeline, high occupancy (5 CTAs/SM -> 20 warps/SM).
// A: fp16 [M,K] row-major.
// B: BKM=false -> fp16 [K,N] row-major; SMEM [k][n], ldmatrix.trans (occ 5)
//    BKM=true  -> fp16 [N,K] row-major; SMEM [n][k], ldmatrix        (occ 4)
// MODE 1: CH = silu(acc + bias[n])                 (fp16 out)
// MODE 2: CH = acc * auxH[m,n]                     (fp16 out)
// MODE 3: C  = (acc + bias[n])*(1+alpha[n]) + auxF (fp32 out)
// MODE 4: C  = acc + bias[z,n] + rel[clamp(m-n)]   (fp32 out)
// ============================================================================
#define AST 40              // A row stride (halfs)
#define MT  64

template <int MODE, bool BKM>
__global__ __launch_bounds__(128, (BKM ? 4 : 5)) void hgemm(
    int K,
    const __half* __restrict__ A, int lda, long sA,
    const __half* __restrict__ B, int ldb, long sB,
    float* __restrict__ C, int ldc, long sC,
    __half* __restrict__ CH, int ldch, long sCh,
    const float* __restrict__ bias,
    const __half* __restrict__ auxH, int ldaux, long sAux,
    const float* __restrict__ auxF,
    const float* __restrict__ alphaP, int sAlpha,
    const float* __restrict__ rel) {
    constexpr int BST = BKM ? 40 : 136;
    constexpr int ASZ2 = MT * AST;               // 2560 halfs per stage
    constexpr int BSZ = BKM ? 128 * 40 : 32 * 136;
    constexpr int STG = ASZ2 + BSZ;              // halfs per stage

    extern __shared__ __half sh[];
    const int z = blockIdx.z;
    A += z * sA; B += z * sB;
    if (MODE == 3 || MODE == 4) C += z * sC;
    if (MODE == 1 || MODE == 2) CH += z * sCh;
    if (MODE == 2) auxH += z * sAux;
    if (MODE == 3) auxF += z * sAux;
    if (MODE == 4) bias += (long)z * LL;
    const float* alpha = (MODE == 3) ? (alphaP + (long)z * sAlpha) : nullptr;

    const int tid = threadIdx.x, wid = tid >> 5, lane = tid & 31;
    const int wn = wid;                          // 4 warps over n (x32 cols)
    const int m0 = blockIdx.y * MT, n0 = blockIdx.x * 128;
    const uint32_t smb = smem_u32(sh);
    const int nk = K >> 5;

    // ---- ldmatrix base addresses (slot 0, k=0), bytes
    uint32_t aAddr[4], bAddr[2];
    #pragma unroll
    for (int mi = 0; mi < 4; mi++) {
        int off = (mi * 16 + (lane & 15)) * AST + ((lane >> 4) << 3);
        aAddr[mi] = smb + off * 2;
    }
    #pragma unroll
    for (int p = 0; p < 2; p++) {
        int off;
        if (BKM) // SMEM [n][k]
            off = (wn * 32 + p * 16 + (lane & 7) + ((lane >> 4) << 3)) * BST
                  + (((lane >> 3) & 1) << 3);
        else     // SMEM [k][n]
            off = (lane & 15) * BST + wn * 32 + p * 16 + ((lane >> 4) << 3);
        bAddr[p] = smb + (ASZ2 + off) * 2;
    }

    // ---- stage loader (slot in {0,1,2})
    auto load_stage = [&](int c, int slot) {
        const uint32_t ab = smb + (uint32_t)(slot * STG) * 2;
        const uint32_t bb = ab + ASZ2 * 2;
        #pragma unroll
        for (int i = 0; i < 2; i++) {                        // A: 64 x 32 halfs
            int v = tid + i * 128;
            int r = v >> 2, ch = v & 3;
            cp16(ab + (uint32_t)(r * AST + ch * 8) * 2,
                 A + (long)(m0 + r) * lda + c * 32 + ch * 8);
        }
        if (BKM) {
            #pragma unroll
            for (int i = 0; i < 4; i++) {                    // B: 128 n-rows x 32 halfs
                int v = tid + i * 128;
                int r = v >> 2, ch = v & 3;
                cp16(bb + (uint32_t)(r * BST + ch * 8) * 2,
                     B + (long)(n0 + r) * ldb + c * 32 + ch * 8);
            }
        } else {
            #pragma unroll
            for (int i = 0; i < 4; i++) {                    // B: 32 k-rows x 128 halfs
                int v = tid + i * 128;
                int r = v >> 4, ch = v & 15;
                cp16(bb + (uint32_t)(r * BST + ch * 8) * 2,
                     B + (long)(c * 32 + r) * ldb + n0 + ch * 8);
            }
        }
    };

    load_stage(0, 0); cp_commit();
    load_stage(1, 1); cp_commit();

    float acc[4][4][4] = {};
    int cs = 0;                                  // compute slot
    for (int c = 0; c < nk; c++) {
        cp_wait<1>();
        __syncthreads();
        if (c + 2 < nk) {
            int ls = cs + 2; if (ls >= 3) ls -= 3;
            load_stage(c + 2, ls);
        }
        cp_commit();

        const uint32_t so = (uint32_t)(cs * STG) * 2;
        #pragma unroll
        for (int kk = 0; kk < 2; kk++) {
            const int ks = kk * 16;
            uint32_t af[4][4], bf[4][2];
            #pragma unroll
            for (int mi = 0; mi < 4; mi++)
                ldm_x4(af[mi], aAddr[mi] + so + ks * 2);
            #pragma unroll
            for (int p = 0; p < 2; p++) {
                uint32_t r4[4];
                if (BKM) ldm_x4(r4, bAddr[p] + so + ks * 2);
                else     ldm_x4_t(r4, bAddr[p] + so + ks * (BST * 2));
                bf[2 * p + 0][0] = r4[0]; bf[2 * p + 0][1] = r4[1];
                bf[2 * p + 1][0] = r4[2]; bf[2 * p + 1][1] = r4[3];
            }
            #pragma unroll
            for (int mi = 0; mi < 4; mi++)
                #pragma unroll
                for (int ni = 0; ni < 4; ni++)
                    mma16816(acc[mi][ni], af[mi], bf[ni]);
        }
        if (++cs == 3) cs = 0;
    }

    // ---- epilogue
    const int g = lane >> 2, t2 = (lane & 3) << 1;
    #pragma unroll
    for (int mi = 0; mi < 4; mi++) {
        #pragma unroll
        for (int half = 0; half < 2; half++) {
            long r = m0 + mi * 16 + g + half * 8;
            #pragma unroll
            for (int ni = 0; ni < 4; ni++) {
                int c = n0 + wn * 32 + ni * 8 + t2;
                float v0 = acc[mi][ni][half * 2 + 0];
                float v1 = acc[mi][ni][half * 2 + 1];
                if (MODE == 1) {
                    v0 = siluf(v0 + bias[c]); v1 = siluf(v1 + bias[c + 1]);
                    *(__half2*)(CH + r * (long)ldch + c) = __floats2half2_rn(v0, v1);
                } else if (MODE == 2) {
                    const __half2 gt = *(const __half2*)(auxH + r * (long)ldaux + c);
                    v0 *= __half2float(gt.x); v1 *= __half2float(gt.y);
                    *(__half2*)(CH + r * (long)ldch + c) = __floats2half2_rn(v0, v1);
                } else if (MODE == 3) {
                    const float2 sres = *(const float2*)(auxF + r * (long)ldaux + c);
                    v0 = (v0 + bias[c]) * (1.f + alpha[c]) + sres.x;
                    v1 = (v1 + bias[c + 1]) * (1.f + alpha[c + 1]) + sres.y;
                    *(float2*)(C + r * (long)ldc + c) = make_float2(v0, v1);
                } else {
                    int d0 = (int)r - c;     d0 = d0 < -64 ? -64 : (d0 > 64 ? 64 : d0);
                    int d1 = (int)r - c - 1; d1 = d1 < -64 ? -64 : (d1 > 64 ? 64 : d1);
                    v0 += bias[c] + rel[d0 + 64];
                    v1 += bias[c + 1] + rel[d1 + 64];
                    *(float2*)(C + r * (long)ldc + c) = make_float2(v0, v1);
                }
            }
        }
    }
}

// ---------------- q/k build + RoPE (reads fp16 h) ----------------------------
__global__ void qk_rope_k(const __half* __restrict__ h, const float* __restrict__ mw,
                          const float* __restrict__ mb, const float* __restrict__ scal,
                          __half* __restrict__ q, __half* __restrict__ k) {
    const int row = blockIdx.x;
    const int t   = threadIdx.x;           // 0..127
    const int pos = row & (LL - 1);
    const __half* base = h + (long)row * GVA_N + 2 * PROJ;
    float b0 = __half2float(base[t]), b1 = __half2float(base[t + 128]);
    float q0 = fmaf(b0, mw[t],       mb[t]);
    float q1 = fmaf(b1, mw[t + 128], mb[t + 128]);
    float k0 = fmaf(b0, mw[256 + t],       mb[256 + t]);
    float k1 = fmaf(b1, mw[256 + t + 128], mb[256 + t + 128]);
    float freq = exp2f(-(float)t * (13.287712379549449f / 128.f));
    float ang = (float)pos * freq;
    float sn, cs; sincosf(ang, &sn, &cs);
    float sc = scal[row];
    q[(long)row * 256 + t]       = __float2half_rn((q0 * cs - q1 * sn) * sc);
    q[(long)row * 256 + t + 128] = __float2half_rn((q1 * cs + q0 * sn) * sc);
    k[(long)row * 256 + t]       = __float2half_rn(k0 * cs - k1 * sn);
    k[(long)row * 256 + t + 128] = __float2half_rn(k1 * cs + k0 * sn);
}

// ---------------- row softmax over 1024: fp16 out, fp32 out optional ---------
__global__ __launch_bounds__(256) void softmax_k(float* __restrict__ S,
                                                 __half* __restrict__ S16,
                                                 int write32) {
    float4* p = (float4*)(S + (long)blockIdx.x * LL);
    __half2* p16 = (__half2*)(S16 + (long)blockIdx.x * LL);
    float4 v = p[threadIdx.x];
    __shared__ float rm[8], rs[8];
    float m = fmaxf(fmaxf(v.x, v.y), fmaxf(v.z, v.w));
    m = warpMax(m);
    if ((threadIdx.x & 31) == 0) rm[threadIdx.x >> 5] = m;
    __syncthreads();
    m = rm[0];
    #pragma unroll
    for (int i = 1; i < 8; i++) m = fmaxf(m, rm[i]);
    v.x = __expf(v.x - m); v.y = __expf(v.y - m);
    v.z = __expf(v.z - m); v.w = __expf(v.w - m);
    float s = v.x + v.y + v.z + v.w;
    s = warpSum(s);
    if ((threadIdx.x & 31) == 0) rs[threadIdx.x >> 5] = s;
    __syncthreads();
    s = 0.f;
    #pragma unroll
    for (int i = 0; i < 8; i++) s += rs[i];
    float inv = 1.f / s;
    v.x *= inv; v.y *= inv; v.z *= inv; v.w *= inv;
    if (write32) p[threadIdx.x] = v;
    p16[threadIdx.x * 2 + 0] = __floats2half2_rn(v.x, v.y);
    p16[threadIdx.x * 2 + 1] = __floats2half2_rn(v.z, v.w);
}

// ---------------- edge = attn[0] + attn[1] (fp32) ----------------------------
__global__ void edge_k(const float* __restrict__ attn, float* __restrict__ e) {
    long i = (long)blockIdx.x * 256 + threadIdx.x;
    float4 a = ((const float4*)attn)[i];
    float4 b = ((const float4*)(attn + (long)LL * LL))[i];
    ((float4*)e)[i] = make_float4(a.x + b.x, a.y + b.y, a.z + b.z, a.w + b.w);
}

// ---------------- launch ------------------------------------------------------
extern "C" void kernel_launch(void* const* d_in, const int* in_sizes, int n_in,
                              void* d_out, int out_size) {
    const float* node      = (const float*)d_in[0];
    const float* qk_scal   = (const float*)d_in[1];
    const float* bias      = (const float*)d_in[2];
    const float* cond      = (const float*)d_in[3];
    const float* w_gva     = (const float*)d_in[4];
    const float* b_gva     = (const float*)d_in[5];
    const float* mhs_w     = (const float*)d_in[6];
    const float* mhs_b     = (const float*)d_in[7];
    const float* relpos    = (const float*)d_in[8];
    const float* w_out     = (const float*)d_in[9];
    const float* b_out     = (const float*)d_in[10];
    const float* w_adaln   = (const float*)d_in[11];
    const float* b_adaln   = (const float*)d_in[12];
    float* out = (float*)d_out;

    float *sc, *part, *gba, *attn, *nodeb;
    __half *x16, *h16, *q16, *k16, *attn16, *av16, *wg16, *wo16;
    cudaGetSymbolAddress((void**)&sc,     d_sc);
    cudaGetSymbolAddress((void**)&part,   d_part);
    cudaGetSymbolAddress((void**)&gba,    d_gba);
    cudaGetSymbolAddress((void**)&x16,    d_x16);
    cudaGetSymbolAddress((void**)&h16,    d_h16);
    cudaGetSymbolAddress((void**)&q16,    d_q16);
    cudaGetSymbolAddress((void**)&k16,    d_k16);
    cudaGetSymbolAddress((void**)&attn,   d_attn);
    cudaGetSymbolAddress((void**)&attn16, d_attn16);
    cudaGetSymbolAddress((void**)&av16,   d_av16);
    cudaGetSymbolAddress((void**)&nodeb,  d_node);
    cudaGetSymbolAddress((void**)&wg16,   d_wgva16);
    cudaGetSymbolAddress((void**)&wo16,   d_wout16);

    const int SMW = 3 * (MT * AST + 32 * 136) * 2;   // 41472 (weights/values B)
    const int SMK = 3 * (MT * AST + 128 * 40) * 2;   // 46080 (k-major B)
    cudaFuncSetAttribute(hgemm<1, false>, cudaFuncAttributeMaxDynamicSharedMemorySize, SMW);
    cudaFuncSetAttribute(hgemm<2, false>, cudaFuncAttributeMaxDynamicSharedMemorySize, SMW);
    cudaFuncSetAttribute(hgemm<3, false>, cudaFuncAttributeMaxDynamicSharedMemorySize, SMW);
    cudaFuncSetAttribute(hgemm<4, true>,  cudaFuncAttributeMaxDynamicSharedMemorySize, SMK);

    cudaMemcpyAsync(nodeb, node, (size_t)ROWS * NODE * sizeof(float),
                    cudaMemcpyDeviceToDevice);
    f2h_k<<<(int)((long)NL * NODE * GVA_N / 1024), 256>>>(w_gva, wg16);
    f2h_k<<<(int)((long)NL * PROJ * NODE / 1024), 256>>>(w_out, wo16);

    silu_vec_k<<<(BB * NODE + 255) / 256, 256>>>(cond, sc, BB * NODE);
    adaln_part_k<<<dim3(ADALN_N / 256, BB * KS, NL), 256>>>(sc, w_adaln, part);
    adaln_reduce_k<<<(NL * BB * ADALN_N) / 256, 256>>>(part, b_adaln, gba);

    for (int l = 0; l < NL; l++) {
        const float* gba_l = gba + (long)l * BB * ADALN_N;

        ln_mod_k<<<ROWS, 256>>>(nodeb, gba_l, x16);

        // h16 = silu(x @ w_gva + b_gva)   [2048 x 5376 x 1280]: 1344 CTAs
        hgemm<1, false><<<dim3(GVA_N / 128, ROWS / MT, 1), 128, SMW>>>(
            NODE,
            x16, NODE, 0L,
            wg16 + (long)l * NODE * GVA_N, GVA_N, 0L,
            nullptr, 0, 0L,
            h16, GVA_N, 0L,
            b_gva + l * GVA_N,
            nullptr, 0, 0L, nullptr, nullptr, 0, nullptr);

        qk_rope_k<<<ROWS, 128>>>(h16, mhs_w + l * 2 * ATTND, mhs_b + l * 2 * ATTND,
                                 qk_scal, q16, k16);

        // logits = q @ k^T + bias + rel   [1024 x 1024 x 256] x2: 256 CTAs
        hgemm<4, true><<<dim3(LL / 128, LL / MT, BB), 128, SMK>>>(
            ATTND,
            q16, ATTND, (long)LL * ATTND,
            k16, ATTND, (long)LL * ATTND,
            attn, LL, (long)LL * LL,
            nullptr, 0, 0L,
            bias,
            nullptr, 0, 0L, nullptr, nullptr, 0,
            relpos + l * NREL);

        softmax_k<<<ROWS, 256>>>(attn, attn16, (l == NL - 1) ? 1 : 0);

        if (l == NL - 1)
            edge_k<<<(LL * LL / 4) / 256, 256>>>(attn, out + (long)ROWS * NODE);

        // av16 = (attn @ values) * gates   [1024 x 2560 x 1024] x2: 640 CTAs
        hgemm<2, false><<<dim3(PROJ / 128, LL / MT, BB), 128, SMW>>>(
            LL,
            attn16, LL, (long)LL * LL,
            h16 + PROJ, GVA_N, (long)LL * GVA_N,
            nullptr, 0, 0L,
            av16, PROJ, (long)LL * PROJ,
            nullptr,
            h16, GVA_N, (long)LL * GVA_N,    // gates fp16
            nullptr, nullptr, 0, nullptr);

        // node = (av @ w_out + b_out)*(1+alpha) + shortcut  [1024 x 1280 x 2560] x2: 320 CTAs
        float* Cdst = (l == NL - 1) ? out : nodeb;
        hgemm<3, false><<<dim3(NODE / 128, LL / MT, BB), 128, SMW>>>(
            PROJ,
            av16, PROJ, (long)LL * PROJ,
            wo16 + (long)l * PROJ * NODE, NODE, 0L,
            Cdst, NODE, (long)LL * NODE,
            nullptr, 0, 0L,
            b_out + l * NODE,
            nullptr, NODE, (long)LL * NODE,
            nodeb,                            // residual fp32
            gba_l + 2 * NODE, ADALN_N, nullptr);
    }
    (void)in_sizes; (void)n_in; (void)out_size;
}